// round 1
// baseline (speedup 1.0000x reference)
#include <cuda_runtime.h>
#include <cstddef>

#define HID 128
#define NS  20000
#define NM  100000
#define NLAYERS 2

#define FLAG_ACC  1
#define FLAG_RELU 2

// ---------------- scratch (static __device__, no allocation) ----------------
__device__ __align__(16) float g_xs0[NS * HID];
__device__ __align__(16) float g_xs1[NS * HID];
__device__ __align__(16) float g_xm0[NM * HID];
__device__ __align__(16) float g_xm1[NM * HID];
__device__ __align__(16) float g_aggm[NM * HID];
__device__ __align__(16) float g_aggs[NS * HID];
__device__ __align__(16) float g_macc[NM * HID];
__device__ __align__(16) float g_xw [NM * HID];
__device__ __align__(16) float g_xw2[NM * HID];
__device__ float g_icm[NM];   // 1/max(count,1) for s2m->m mean
__device__ float g_ics[NS];   // 1/max(count,1) for s2m rev mean
__device__ float g_dF [NM];   // rsqrt(deg_fwd+1)
__device__ float g_dR [NM];   // rsqrt(deg_rev+1)

// ---------------- helpers ----------------
__device__ __forceinline__ void red4(float* p, float x, float y, float z, float w) {
    asm volatile("red.global.add.v4.f32 [%0], {%1,%2,%3,%4};"
                 :: "l"(p), "f"(x), "f"(y), "f"(z), "f"(w) : "memory");
}

// ---------------- small kernels ----------------
__global__ void zero4_kernel(float* __restrict__ p, size_t n4) {
    size_t i = (size_t)blockIdx.x * blockDim.x + threadIdx.x;
    if (i < n4) reinterpret_cast<float4*>(p)[i] = make_float4(0.f, 0.f, 0.f, 0.f);
}

__global__ void count_kernel(const int* __restrict__ idx, float* __restrict__ cnt, int E) {
    int t = blockIdx.x * blockDim.x + threadIdx.x;
    if (t < E) atomicAdd(&cnt[idx[t]], 1.0f);
}

__global__ void finalize_deg_kernel() {
    int i = blockIdx.x * blockDim.x + threadIdx.x;
    if (i < NM) {
        g_icm[i] = 1.0f / fmaxf(g_icm[i], 1.0f);
        g_dF[i]  = rsqrtf(g_dF[i] + 1.0f);
        g_dR[i]  = rsqrtf(g_dR[i] + 1.0f);
    }
    if (i < NS) g_ics[i] = 1.0f / fmaxf(g_ics[i], 1.0f);
}

// mean-agg numerator: AGG[dst] += X[src]   (one warp per edge, float4 lanes)
__global__ void __launch_bounds__(256) scatter_sum_kernel(
    const int* __restrict__ src, const int* __restrict__ dst,
    const float* __restrict__ X, float* __restrict__ AGG, int E)
{
    long long t = (long long)blockIdx.x * blockDim.x + threadIdx.x;
    int e = (int)(t >> 5);
    if (e >= E) return;
    int lane = (int)(t & 31);
    int s = src[e], d = dst[e];
    float4 v = *reinterpret_cast<const float4*>(&X[(size_t)s * HID + lane * 4]);
    red4(&AGG[(size_t)d * HID + lane * 4], v.x, v.y, v.z, v.w);
}

// GCN fwd + rev in one pass over m2m edges:
//   MACC[d] += dF[s]*dF[d] * XW[s]     (fwd: src->dst)
//   MACC[s] += dR[s]*dR[d] * XW2[d]    (rev: dst->src)
__global__ void __launch_bounds__(256) gcn_scatter_kernel(
    const int* __restrict__ src, const int* __restrict__ dst,
    const float* __restrict__ XW, const float* __restrict__ XW2,
    float* __restrict__ MACC, int E)
{
    long long t = (long long)blockIdx.x * blockDim.x + threadIdx.x;
    int e = (int)(t >> 5);
    if (e >= E) return;
    int lane = (int)(t & 31);
    int s = src[e], d = dst[e];
    float wF = g_dF[s] * g_dF[d];
    float wR = g_dR[s] * g_dR[d];
    size_t so = (size_t)s * HID + lane * 4;
    size_t dof = (size_t)d * HID + lane * 4;
    float4 a = *reinterpret_cast<const float4*>(&XW[so]);
    red4(&MACC[dof], wF * a.x, wF * a.y, wF * a.z, wF * a.w);
    float4 b = *reinterpret_cast<const float4*>(&XW2[dof]);
    red4(&MACC[so], wR * b.x, wR * b.y, wR * b.z, wR * b.w);
}

// out = relu(MACC + dF^2*XW + bF + dR^2*XW2 + bR)
__global__ void finalize_m_kernel(
    const float* __restrict__ bF, const float* __restrict__ bR,
    float* __restrict__ out)
{
    size_t idx = (size_t)blockIdx.x * blockDim.x + threadIdx.x;  // float4 units
    size_t n4 = (size_t)NM * (HID / 4);
    if (idx >= n4) return;
    int row = (int)(idx >> 5);
    int c4  = (int)(idx & 31);
    float f2 = g_dF[row] * g_dF[row];
    float r2 = g_dR[row] * g_dR[row];
    float4 m  = reinterpret_cast<const float4*>(g_macc)[idx];
    float4 a  = reinterpret_cast<const float4*>(g_xw)[idx];
    float4 b  = reinterpret_cast<const float4*>(g_xw2)[idx];
    float4 bf = reinterpret_cast<const float4*>(bF)[c4];
    float4 br = reinterpret_cast<const float4*>(bR)[c4];
    float4 o;
    o.x = fmaxf(m.x + f2 * a.x + bf.x + r2 * b.x + br.x, 0.f);
    o.y = fmaxf(m.y + f2 * a.y + bf.y + r2 * b.y + br.y, 0.f);
    o.z = fmaxf(m.z + f2 * a.z + bf.z + r2 * b.z + br.z, 0.f);
    o.w = fmaxf(m.w + f2 * a.w + bf.w + r2 * b.w + br.w, 0.f);
    reinterpret_cast<float4*>(out)[idx] = o;
}

// ---------------- GEMM: D[M,128] (+)= rowscale .* (A[M,128] @ B[128,128]) + bias ----------------
__global__ void __launch_bounds__(256) gemm_k128(
    const float* __restrict__ A, const float* __restrict__ B,
    float* __restrict__ D, int M,
    const float* __restrict__ rowscale, const float* __restrict__ bias, int flags)
{
    __shared__ float As[64][33];
    __shared__ float Bs[32][128];
    int tid = threadIdx.x;
    int tx = tid & 15;          // 16 col-groups of 8
    int ty = tid >> 4;          // 16 row-groups of 4
    int r0 = blockIdx.x * 64;

    float acc[4][8];
#pragma unroll
    for (int i = 0; i < 4; i++)
#pragma unroll
        for (int j = 0; j < 8; j++) acc[i][j] = 0.f;

    for (int k0 = 0; k0 < 128; k0 += 32) {
#pragma unroll
        for (int it = 0; it < 2; it++) {
            int idx = tid + it * 256;        // 0..511
            int row = idx >> 3, kq = idx & 7;
            float4 v = make_float4(0.f, 0.f, 0.f, 0.f);
            if (r0 + row < M)
                v = *reinterpret_cast<const float4*>(&A[(size_t)(r0 + row) * 128 + k0 + kq * 4]);
            As[row][kq * 4 + 0] = v.x;
            As[row][kq * 4 + 1] = v.y;
            As[row][kq * 4 + 2] = v.z;
            As[row][kq * 4 + 3] = v.w;
        }
#pragma unroll
        for (int it = 0; it < 4; it++) {
            int idx = tid + it * 256;        // 0..1023
            int kr = idx >> 5, c4 = idx & 31;
            *reinterpret_cast<float4*>(&Bs[kr][c4 * 4]) =
                *reinterpret_cast<const float4*>(&B[(size_t)(k0 + kr) * 128 + c4 * 4]);
        }
        __syncthreads();
#pragma unroll
        for (int k = 0; k < 32; k++) {
            float a[4];
#pragma unroll
            for (int i = 0; i < 4; i++) a[i] = As[ty * 4 + i][k];
            float4 b0 = *reinterpret_cast<const float4*>(&Bs[k][tx * 8]);
            float4 b1 = *reinterpret_cast<const float4*>(&Bs[k][tx * 8 + 4]);
            float b[8] = {b0.x, b0.y, b0.z, b0.w, b1.x, b1.y, b1.z, b1.w};
#pragma unroll
            for (int i = 0; i < 4; i++)
#pragma unroll
                for (int j = 0; j < 8; j++) acc[i][j] += a[i] * b[j];
        }
        __syncthreads();
    }

    float bv[8];
    if (bias) {
        float4 bb0 = *reinterpret_cast<const float4*>(&bias[tx * 8]);
        float4 bb1 = *reinterpret_cast<const float4*>(&bias[tx * 8 + 4]);
        bv[0]=bb0.x; bv[1]=bb0.y; bv[2]=bb0.z; bv[3]=bb0.w;
        bv[4]=bb1.x; bv[5]=bb1.y; bv[6]=bb1.z; bv[7]=bb1.w;
    } else {
#pragma unroll
        for (int j = 0; j < 8; j++) bv[j] = 0.f;
    }

#pragma unroll
    for (int i = 0; i < 4; i++) {
        int row = r0 + ty * 4 + i;
        if (row >= M) continue;
        float sc = rowscale ? rowscale[row] : 1.0f;
        float o[8];
#pragma unroll
        for (int j = 0; j < 8; j++) o[j] = acc[i][j] * sc + bv[j];
        float* dp = &D[(size_t)row * 128 + tx * 8];
        if (flags & FLAG_ACC) {
            float4 d0 = *reinterpret_cast<const float4*>(dp);
            float4 d1 = *reinterpret_cast<const float4*>(dp + 4);
            o[0]+=d0.x; o[1]+=d0.y; o[2]+=d0.z; o[3]+=d0.w;
            o[4]+=d1.x; o[5]+=d1.y; o[6]+=d1.z; o[7]+=d1.w;
        }
        if (flags & FLAG_RELU) {
#pragma unroll
            for (int j = 0; j < 8; j++) o[j] = fmaxf(o[j], 0.f);
        }
        *reinterpret_cast<float4*>(dp)     = make_float4(o[0], o[1], o[2], o[3]);
        *reinterpret_cast<float4*>(dp + 4) = make_float4(o[4], o[5], o[6], o[7]);
    }
}

// ---------------- classifier: out[e] = dot(XS[ls[e]], XM[ld[e]]) ----------------
__global__ void __launch_bounds__(256) classify_kernel(
    const int* __restrict__ ls, const int* __restrict__ ld,
    const float* __restrict__ XS, const float* __restrict__ XM,
    float* __restrict__ out, int E)
{
    long long t = (long long)blockIdx.x * blockDim.x + threadIdx.x;
    int e = (int)(t >> 5);
    if (e >= E) return;
    int lane = (int)(t & 31);
    int s = ls[e], d = ld[e];
    float4 a = *reinterpret_cast<const float4*>(&XS[(size_t)s * HID + lane * 4]);
    float4 b = *reinterpret_cast<const float4*>(&XM[(size_t)d * HID + lane * 4]);
    float p = a.x * b.x + a.y * b.y + a.z * b.z + a.w * b.w;
#pragma unroll
    for (int o = 16; o > 0; o >>= 1) p += __shfl_xor_sync(0xffffffffu, p, o);
    if (lane == 0) out[e] = p;
}

// ---------------- host ----------------
static inline void zero4(float* p, size_t n) {
    size_t n4 = n / 4;
    zero4_kernel<<<(unsigned)((n4 + 255) / 256), 256>>>(p, n4);
}

extern "C" void kernel_launch(void* const* d_in, const int* in_sizes, int n_in,
                              void* d_out, int out_size)
{
    const int*   s2m_src = (const int*)d_in[0];
    const int*   s2m_dst = (const int*)d_in[1];
    const int*   m2m_src = (const int*)d_in[2];
    const int*   m2m_dst = (const int*)d_in[3];
    const int*   lbl_src = (const int*)d_in[4];
    const int*   lbl_dst = (const int*)d_in[5];
    const float* srna    = (const float*)d_in[6];
    const float* mrna    = (const float*)d_in[7];
    const float* sWl     = (const float*)d_in[8];
    const float* sbl     = (const float*)d_in[9];
    const float* sWr     = (const float*)d_in[10];
    const float* rWl     = (const float*)d_in[11];
    const float* rbl     = (const float*)d_in[12];
    const float* rWr     = (const float*)d_in[13];
    const float* gFW     = (const float*)d_in[14];
    const float* gFb     = (const float*)d_in[15];
    const float* gRW     = (const float*)d_in[16];
    const float* gRb     = (const float*)d_in[17];

    const int Es2m = in_sizes[0];
    const int Em2m = in_sizes[2];
    const int Elbl = in_sizes[4];

    float *xs0, *xs1, *xm0, *xm1, *aggm, *aggs, *macc, *xw, *xw2, *icm, *ics, *dF, *dR;
    cudaGetSymbolAddress((void**)&xs0, g_xs0);
    cudaGetSymbolAddress((void**)&xs1, g_xs1);
    cudaGetSymbolAddress((void**)&xm0, g_xm0);
    cudaGetSymbolAddress((void**)&xm1, g_xm1);
    cudaGetSymbolAddress((void**)&aggm, g_aggm);
    cudaGetSymbolAddress((void**)&aggs, g_aggs);
    cudaGetSymbolAddress((void**)&macc, g_macc);
    cudaGetSymbolAddress((void**)&xw, g_xw);
    cudaGetSymbolAddress((void**)&xw2, g_xw2);
    cudaGetSymbolAddress((void**)&icm, g_icm);
    cudaGetSymbolAddress((void**)&ics, g_ics);
    cudaGetSymbolAddress((void**)&dF, g_dF);
    cudaGetSymbolAddress((void**)&dR, g_dR);

    // degrees / counts (recomputed every call; deterministic w.r.t. inputs)
    zero4(icm, NM); zero4(ics, NS); zero4(dF, NM); zero4(dR, NM);
    count_kernel<<<(Es2m + 255) / 256, 256>>>(s2m_dst, icm, Es2m);
    count_kernel<<<(Es2m + 255) / 256, 256>>>(s2m_src, ics, Es2m);
    count_kernel<<<(Em2m + 255) / 256, 256>>>(m2m_dst, dF, Em2m);
    count_kernel<<<(Em2m + 255) / 256, 256>>>(m2m_src, dR, Em2m);
    finalize_deg_kernel<<<(NM + 255) / 256, 256>>>();

    const float* xsi = srna;
    const float* xmi = mrna;
    const size_t WSZ = (size_t)HID * HID;

    for (int l = 0; l < NLAYERS; l++) {
        float* xso = (l == 0) ? xs0 : xs1;
        float* xmo = (l == 0) ? xm0 : xm1;

        // ---- mRNA side ----
        zero4(aggm, (size_t)NM * HID);
        {
            long long th = (long long)Es2m * 32;
            scatter_sum_kernel<<<(unsigned)((th + 255) / 256), 256>>>(s2m_src, s2m_dst, xsi, aggm, Es2m);
        }
        unsigned gm = (NM + 63) / 64;
        gemm_k128<<<gm, 256>>>(xmi,  sWr + l * WSZ, macc, NM, nullptr, nullptr, 0);
        gemm_k128<<<gm, 256>>>(aggm, sWl + l * WSZ, macc, NM, icm, sbl + l * HID, FLAG_ACC);
        gemm_k128<<<gm, 256>>>(xmi,  gFW + l * WSZ, xw,   NM, nullptr, nullptr, 0);
        gemm_k128<<<gm, 256>>>(xmi,  gRW + l * WSZ, xw2,  NM, nullptr, nullptr, 0);
        {
            long long th = (long long)Em2m * 32;
            gcn_scatter_kernel<<<(unsigned)((th + 255) / 256), 256>>>(m2m_src, m2m_dst, xw, xw2, macc, Em2m);
        }
        {
            size_t n4 = (size_t)NM * (HID / 4);
            finalize_m_kernel<<<(unsigned)((n4 + 255) / 256), 256>>>(gFb + l * HID, gRb + l * HID, xmo);
        }

        // ---- sRNA side (uses OLD x_m) ----
        zero4(aggs, (size_t)NS * HID);
        {
            long long th = (long long)Es2m * 32;
            scatter_sum_kernel<<<(unsigned)((th + 255) / 256), 256>>>(s2m_dst, s2m_src, xmi, aggs, Es2m);
        }
        unsigned gs = (NS + 63) / 64;
        gemm_k128<<<gs, 256>>>(xsi,  rWr + l * WSZ, xso, NS, nullptr, nullptr, 0);
        gemm_k128<<<gs, 256>>>(aggs, rWl + l * WSZ, xso, NS, ics, rbl + l * HID, FLAG_ACC | FLAG_RELU);

        xsi = xso;
        xmi = xmo;
    }

    {
        long long th = (long long)Elbl * 32;
        classify_kernel<<<(unsigned)((th + 255) / 256), 256>>>(lbl_src, lbl_dst, xsi, xmi, (float*)d_out, Elbl);
    }
}

// round 2
// speedup vs baseline: 1.3264x; 1.3264x over previous
#include <cuda_runtime.h>
#include <cstddef>

#define HID 128
#define NS  20000
#define NM  100000
#define ES2M 1000000
#define EM2M 2000000
#define NLAYERS 2

#define FLAG_ACC  1
#define FLAG_RELU 2

// ---------------- scratch (static __device__, no allocation) ----------------
__device__ __align__(16) float g_xs0[NS * HID];
__device__ __align__(16) float g_xs1[NS * HID];
__device__ __align__(16) float g_xm0[NM * HID];
__device__ __align__(16) float g_xm1[NM * HID];
__device__ __align__(16) float g_aggm[NM * HID];
__device__ __align__(16) float g_aggs[NS * HID];
__device__ __align__(16) float g_macc[NM * HID];
__device__ __align__(16) float g_xw [NM * HID];
__device__ __align__(16) float g_xw2[NM * HID];
__device__ float g_dF [NM];   // rsqrt(deg_fwd+1)
__device__ float g_dR [NM];   // rsqrt(deg_rev+1)

// CSR scratch
__device__ int g_cntMd[NM];        // s2m grouped by dst (mRNA)
__device__ int g_cntSs[NS];        // s2m grouped by src (sRNA)
__device__ int g_cntF [NM];        // m2m grouped by dst
__device__ int g_cntR [NM];        // m2m grouped by src
__device__ int g_offMd[NM + 1];
__device__ int g_offSs[NS + 1];
__device__ int g_offF [NM + 1];
__device__ int g_offR [NM + 1];
__device__ int g_curMd[NM];
__device__ int g_curSs[NS];
__device__ int g_curF [NM];
__device__ int g_curR [NM];
__device__ int g_lstMd[ES2M];      // partner (src sRNA id)
__device__ int g_lstSs[ES2M];      // partner (dst mRNA id)
__device__ int g_lstF [EM2M];      // partner (src)
__device__ int g_lstR [EM2M];      // partner (dst)

// ---------------- CSR build ----------------
__global__ void zero_counts_kernel() {
    int i = blockIdx.x * blockDim.x + threadIdx.x;
    if (i < NM) { g_cntMd[i] = 0; g_cntF[i] = 0; g_cntR[i] = 0; }
    if (i < NS) { g_cntSs[i] = 0; }
}

__global__ void hist_s2m_kernel(const int* __restrict__ src, const int* __restrict__ dst, int E) {
    int e = blockIdx.x * blockDim.x + threadIdx.x;
    if (e >= E) return;
    atomicAdd(&g_cntMd[dst[e]], 1);
    atomicAdd(&g_cntSs[src[e]], 1);
}

__global__ void hist_m2m_kernel(const int* __restrict__ src, const int* __restrict__ dst, int E) {
    int e = blockIdx.x * blockDim.x + threadIdx.x;
    if (e >= E) return;
    atomicAdd(&g_cntF[dst[e]], 1);
    atomicAdd(&g_cntR[src[e]], 1);
}

// block-wide (1024-thread) chunked exclusive scan; writes off[0..n] and cursor copy
__device__ void scan_one(const int* __restrict__ cnt, int n,
                         int* __restrict__ off, int* __restrict__ cur)
{
    __shared__ int warpsums[32];
    __shared__ int s_carry;
    int tid = threadIdx.x, lane = tid & 31, wid = tid >> 5;
    if (tid == 0) s_carry = 0;
    __syncthreads();
    for (int base = 0; base < n; base += 1024) {
        int i = base + tid;
        int v = (i < n) ? cnt[i] : 0;
        int x = v;
#pragma unroll
        for (int o = 1; o < 32; o <<= 1) {
            int t = __shfl_up_sync(0xffffffffu, x, o);
            if (lane >= o) x += t;
        }
        if (lane == 31) warpsums[wid] = x;
        __syncthreads();
        if (wid == 0) {
            int w = warpsums[lane];
#pragma unroll
            for (int o = 1; o < 32; o <<= 1) {
                int t = __shfl_up_sync(0xffffffffu, w, o);
                if (lane >= o) w += t;
            }
            warpsums[lane] = w;
        }
        __syncthreads();
        int carry = s_carry;
        int wpref = wid ? warpsums[wid - 1] : 0;
        int excl = x - v + wpref + carry;
        if (i < n) { off[i] = excl; cur[i] = excl; }
        int total = warpsums[31];
        __syncthreads();
        if (tid == 1023) s_carry = carry + total;
        __syncthreads();
    }
    if (tid == 0) off[n] = s_carry;
}

__global__ void scan4_kernel() {
    switch (blockIdx.x) {
        case 0: scan_one(g_cntMd, NM, g_offMd, g_curMd); break;
        case 1: scan_one(g_cntSs, NS, g_offSs, g_curSs); break;
        case 2: scan_one(g_cntF,  NM, g_offF,  g_curF ); break;
        case 3: scan_one(g_cntR,  NM, g_offR,  g_curR ); break;
    }
}

__global__ void fill_s2m_kernel(const int* __restrict__ src, const int* __restrict__ dst, int E) {
    int e = blockIdx.x * blockDim.x + threadIdx.x;
    if (e >= E) return;
    int s = src[e], d = dst[e];
    g_lstMd[atomicAdd(&g_curMd[d], 1)] = s;
    g_lstSs[atomicAdd(&g_curSs[s], 1)] = d;
}

__global__ void fill_m2m_kernel(const int* __restrict__ src, const int* __restrict__ dst, int E) {
    int e = blockIdx.x * blockDim.x + threadIdx.x;
    if (e >= E) return;
    int s = src[e], d = dst[e];
    g_lstF[atomicAdd(&g_curF[d], 1)] = s;
    g_lstR[atomicAdd(&g_curR[s], 1)] = d;
}

__global__ void deg_kernel() {
    int i = blockIdx.x * blockDim.x + threadIdx.x;
    if (i < NM) {
        g_dF[i] = rsqrtf((float)g_cntF[i] + 1.0f);
        g_dR[i] = rsqrtf((float)g_cntR[i] + 1.0f);
    }
}

// ---------------- gathers (warp per dst row, no atomics) ----------------
// OUT[row] = mean over CSR neighbors of X[p]
__global__ void __launch_bounds__(256) gather_mean_kernel(
    const int* __restrict__ off, const int* __restrict__ lst,
    const float* __restrict__ X, float* __restrict__ OUT, int n)
{
    int w = (blockIdx.x * blockDim.x + threadIdx.x) >> 5;
    if (w >= n) return;
    int lane = threadIdx.x & 31;
    int s = off[w], e = off[w + 1];
    float4 a0 = make_float4(0.f, 0.f, 0.f, 0.f);
    float4 a1 = make_float4(0.f, 0.f, 0.f, 0.f);
    int i = s;
    for (; i + 1 < e; i += 2) {
        int p0 = lst[i], p1 = lst[i + 1];
        float4 v0 = *reinterpret_cast<const float4*>(&X[(size_t)p0 * HID + lane * 4]);
        float4 v1 = *reinterpret_cast<const float4*>(&X[(size_t)p1 * HID + lane * 4]);
        a0.x += v0.x; a0.y += v0.y; a0.z += v0.z; a0.w += v0.w;
        a1.x += v1.x; a1.y += v1.y; a1.z += v1.z; a1.w += v1.w;
    }
    if (i < e) {
        int p0 = lst[i];
        float4 v0 = *reinterpret_cast<const float4*>(&X[(size_t)p0 * HID + lane * 4]);
        a0.x += v0.x; a0.y += v0.y; a0.z += v0.z; a0.w += v0.w;
    }
    float inv = 1.0f / fmaxf((float)(e - s), 1.0f);
    float4 o;
    o.x = (a0.x + a1.x) * inv; o.y = (a0.y + a1.y) * inv;
    o.z = (a0.z + a1.z) * inv; o.w = (a0.w + a1.w) * inv;
    *reinterpret_cast<float4*>(&OUT[(size_t)w * HID + lane * 4]) = o;
}

// MACC[row] += dinv[row] * sum_p dinv[p] * X[p]
__global__ void __launch_bounds__(256) gather_gcn_kernel(
    const int* __restrict__ off, const int* __restrict__ lst,
    const float* __restrict__ X, const float* __restrict__ dinv,
    float* __restrict__ MACC, int n)
{
    int w = (blockIdx.x * blockDim.x + threadIdx.x) >> 5;
    if (w >= n) return;
    int lane = threadIdx.x & 31;
    int s = off[w], e = off[w + 1];
    float4 a0 = make_float4(0.f, 0.f, 0.f, 0.f);
    float4 a1 = make_float4(0.f, 0.f, 0.f, 0.f);
    int i = s;
    for (; i + 1 < e; i += 2) {
        int p0 = lst[i], p1 = lst[i + 1];
        float w0 = dinv[p0], w1 = dinv[p1];
        float4 v0 = *reinterpret_cast<const float4*>(&X[(size_t)p0 * HID + lane * 4]);
        float4 v1 = *reinterpret_cast<const float4*>(&X[(size_t)p1 * HID + lane * 4]);
        a0.x += w0 * v0.x; a0.y += w0 * v0.y; a0.z += w0 * v0.z; a0.w += w0 * v0.w;
        a1.x += w1 * v1.x; a1.y += w1 * v1.y; a1.z += w1 * v1.z; a1.w += w1 * v1.w;
    }
    if (i < e) {
        int p0 = lst[i];
        float w0 = dinv[p0];
        float4 v0 = *reinterpret_cast<const float4*>(&X[(size_t)p0 * HID + lane * 4]);
        a0.x += w0 * v0.x; a0.y += w0 * v0.y; a0.z += w0 * v0.z; a0.w += w0 * v0.w;
    }
    float dr = dinv[w];
    float* mp = &MACC[(size_t)w * HID + lane * 4];
    float4 m = *reinterpret_cast<const float4*>(mp);
    m.x += dr * (a0.x + a1.x); m.y += dr * (a0.y + a1.y);
    m.z += dr * (a0.z + a1.z); m.w += dr * (a0.w + a1.w);
    *reinterpret_cast<float4*>(mp) = m;
}

// out = relu(MACC + dF^2*XW + bF + dR^2*XW2 + bR)
__global__ void finalize_m_kernel(
    const float* __restrict__ bF, const float* __restrict__ bR,
    float* __restrict__ out)
{
    size_t idx = (size_t)blockIdx.x * blockDim.x + threadIdx.x;  // float4 units
    size_t n4 = (size_t)NM * (HID / 4);
    if (idx >= n4) return;
    int row = (int)(idx >> 5);
    int c4  = (int)(idx & 31);
    float f2 = g_dF[row] * g_dF[row];
    float r2 = g_dR[row] * g_dR[row];
    float4 m  = reinterpret_cast<const float4*>(g_macc)[idx];
    float4 a  = reinterpret_cast<const float4*>(g_xw)[idx];
    float4 b  = reinterpret_cast<const float4*>(g_xw2)[idx];
    float4 bf = reinterpret_cast<const float4*>(bF)[c4];
    float4 br = reinterpret_cast<const float4*>(bR)[c4];
    float4 o;
    o.x = fmaxf(m.x + f2 * a.x + bf.x + r2 * b.x + br.x, 0.f);
    o.y = fmaxf(m.y + f2 * a.y + bf.y + r2 * b.y + br.y, 0.f);
    o.z = fmaxf(m.z + f2 * a.z + bf.z + r2 * b.z + br.z, 0.f);
    o.w = fmaxf(m.w + f2 * a.w + bf.w + r2 * b.w + br.w, 0.f);
    reinterpret_cast<float4*>(out)[idx] = o;
}

// ---------------- GEMM: D[M,128] (+)= (A[M,128] @ B[128,128]) + bias ----------------
__global__ void __launch_bounds__(256) gemm_k128(
    const float* __restrict__ A, const float* __restrict__ B,
    float* __restrict__ D, int M,
    const float* __restrict__ bias, int flags)
{
    __shared__ float As[64][33];
    __shared__ float Bs[32][128];
    int tid = threadIdx.x;
    int tx = tid & 15;          // 16 col-groups of 8
    int ty = tid >> 4;          // 16 row-groups of 4
    int r0 = blockIdx.x * 64;

    float acc[4][8];
#pragma unroll
    for (int i = 0; i < 4; i++)
#pragma unroll
        for (int j = 0; j < 8; j++) acc[i][j] = 0.f;

    for (int k0 = 0; k0 < 128; k0 += 32) {
#pragma unroll
        for (int it = 0; it < 2; it++) {
            int idx = tid + it * 256;        // 0..511
            int row = idx >> 3, kq = idx & 7;
            float4 v = make_float4(0.f, 0.f, 0.f, 0.f);
            if (r0 + row < M)
                v = *reinterpret_cast<const float4*>(&A[(size_t)(r0 + row) * 128 + k0 + kq * 4]);
            As[row][kq * 4 + 0] = v.x;
            As[row][kq * 4 + 1] = v.y;
            As[row][kq * 4 + 2] = v.z;
            As[row][kq * 4 + 3] = v.w;
        }
#pragma unroll
        for (int it = 0; it < 4; it++) {
            int idx = tid + it * 256;        // 0..1023
            int kr = idx >> 5, c4 = idx & 31;
            *reinterpret_cast<float4*>(&Bs[kr][c4 * 4]) =
                *reinterpret_cast<const float4*>(&B[(size_t)(k0 + kr) * 128 + c4 * 4]);
        }
        __syncthreads();
#pragma unroll
        for (int k = 0; k < 32; k++) {
            float a[4];
#pragma unroll
            for (int i = 0; i < 4; i++) a[i] = As[ty * 4 + i][k];
            float4 b0 = *reinterpret_cast<const float4*>(&Bs[k][tx * 8]);
            float4 b1 = *reinterpret_cast<const float4*>(&Bs[k][tx * 8 + 4]);
            float b[8] = {b0.x, b0.y, b0.z, b0.w, b1.x, b1.y, b1.z, b1.w};
#pragma unroll
            for (int i = 0; i < 4; i++)
#pragma unroll
                for (int j = 0; j < 8; j++) acc[i][j] += a[i] * b[j];
        }
        __syncthreads();
    }

    float bv[8];
    if (bias) {
        float4 bb0 = *reinterpret_cast<const float4*>(&bias[tx * 8]);
        float4 bb1 = *reinterpret_cast<const float4*>(&bias[tx * 8 + 4]);
        bv[0]=bb0.x; bv[1]=bb0.y; bv[2]=bb0.z; bv[3]=bb0.w;
        bv[4]=bb1.x; bv[5]=bb1.y; bv[6]=bb1.z; bv[7]=bb1.w;
    } else {
#pragma unroll
        for (int j = 0; j < 8; j++) bv[j] = 0.f;
    }

#pragma unroll
    for (int i = 0; i < 4; i++) {
        int row = r0 + ty * 4 + i;
        if (row >= M) continue;
        float o[8];
#pragma unroll
        for (int j = 0; j < 8; j++) o[j] = acc[i][j] + bv[j];
        float* dp = &D[(size_t)row * 128 + tx * 8];
        if (flags & FLAG_ACC) {
            float4 d0 = *reinterpret_cast<const float4*>(dp);
            float4 d1 = *reinterpret_cast<const float4*>(dp + 4);
            o[0]+=d0.x; o[1]+=d0.y; o[2]+=d0.z; o[3]+=d0.w;
            o[4]+=d1.x; o[5]+=d1.y; o[6]+=d1.z; o[7]+=d1.w;
        }
        if (flags & FLAG_RELU) {
#pragma unroll
            for (int j = 0; j < 8; j++) o[j] = fmaxf(o[j], 0.f);
        }
        *reinterpret_cast<float4*>(dp)     = make_float4(o[0], o[1], o[2], o[3]);
        *reinterpret_cast<float4*>(dp + 4) = make_float4(o[4], o[5], o[6], o[7]);
    }
}

// ---------------- classifier: out[e] = dot(XS[ls[e]], XM[ld[e]]) ----------------
__global__ void __launch_bounds__(256) classify_kernel(
    const int* __restrict__ ls, const int* __restrict__ ld,
    const float* __restrict__ XS, const float* __restrict__ XM,
    float* __restrict__ out, int E)
{
    long long t = (long long)blockIdx.x * blockDim.x + threadIdx.x;
    int e = (int)(t >> 5);
    if (e >= E) return;
    int lane = (int)(t & 31);
    int s = ls[e], d = ld[e];
    float4 a = *reinterpret_cast<const float4*>(&XS[(size_t)s * HID + lane * 4]);
    float4 b = *reinterpret_cast<const float4*>(&XM[(size_t)d * HID + lane * 4]);
    float p = a.x * b.x + a.y * b.y + a.z * b.z + a.w * b.w;
#pragma unroll
    for (int o = 16; o > 0; o >>= 1) p += __shfl_xor_sync(0xffffffffu, p, o);
    if (lane == 0) out[e] = p;
}

// ---------------- host ----------------
extern "C" void kernel_launch(void* const* d_in, const int* in_sizes, int n_in,
                              void* d_out, int out_size)
{
    const int*   s2m_src = (const int*)d_in[0];
    const int*   s2m_dst = (const int*)d_in[1];
    const int*   m2m_src = (const int*)d_in[2];
    const int*   m2m_dst = (const int*)d_in[3];
    const int*   lbl_src = (const int*)d_in[4];
    const int*   lbl_dst = (const int*)d_in[5];
    const float* srna    = (const float*)d_in[6];
    const float* mrna    = (const float*)d_in[7];
    const float* sWl     = (const float*)d_in[8];
    const float* sbl     = (const float*)d_in[9];
    const float* sWr     = (const float*)d_in[10];
    const float* rWl     = (const float*)d_in[11];
    const float* rbl     = (const float*)d_in[12];
    const float* rWr     = (const float*)d_in[13];
    const float* gFW     = (const float*)d_in[14];
    const float* gFb     = (const float*)d_in[15];
    const float* gRW     = (const float*)d_in[16];
    const float* gRb     = (const float*)d_in[17];

    const int Es2m = in_sizes[0];
    const int Em2m = in_sizes[2];
    const int Elbl = in_sizes[4];

    float *xs0, *xs1, *xm0, *xm1, *aggm, *aggs, *macc, *xw, *xw2, *dF, *dR;
    int *offMd, *offSs, *offF, *offR, *lstMd, *lstSs, *lstF, *lstR;
    cudaGetSymbolAddress((void**)&xs0, g_xs0);
    cudaGetSymbolAddress((void**)&xs1, g_xs1);
    cudaGetSymbolAddress((void**)&xm0, g_xm0);
    cudaGetSymbolAddress((void**)&xm1, g_xm1);
    cudaGetSymbolAddress((void**)&aggm, g_aggm);
    cudaGetSymbolAddress((void**)&aggs, g_aggs);
    cudaGetSymbolAddress((void**)&macc, g_macc);
    cudaGetSymbolAddress((void**)&xw, g_xw);
    cudaGetSymbolAddress((void**)&xw2, g_xw2);
    cudaGetSymbolAddress((void**)&dF, g_dF);
    cudaGetSymbolAddress((void**)&dR, g_dR);
    cudaGetSymbolAddress((void**)&offMd, g_offMd);
    cudaGetSymbolAddress((void**)&offSs, g_offSs);
    cudaGetSymbolAddress((void**)&offF, g_offF);
    cudaGetSymbolAddress((void**)&offR, g_offR);
    cudaGetSymbolAddress((void**)&lstMd, g_lstMd);
    cudaGetSymbolAddress((void**)&lstSs, g_lstSs);
    cudaGetSymbolAddress((void**)&lstF, g_lstF);
    cudaGetSymbolAddress((void**)&lstR, g_lstR);

    // ---- CSR build (per-call, deterministic w.r.t. inputs) ----
    zero_counts_kernel<<<(NM + 255) / 256, 256>>>();
    hist_s2m_kernel<<<(Es2m + 255) / 256, 256>>>(s2m_src, s2m_dst, Es2m);
    hist_m2m_kernel<<<(Em2m + 255) / 256, 256>>>(m2m_src, m2m_dst, Em2m);
    scan4_kernel<<<4, 1024>>>();
    fill_s2m_kernel<<<(Es2m + 255) / 256, 256>>>(s2m_src, s2m_dst, Es2m);
    fill_m2m_kernel<<<(Em2m + 255) / 256, 256>>>(m2m_src, m2m_dst, Em2m);
    deg_kernel<<<(NM + 255) / 256, 256>>>();

    const float* xsi = srna;
    const float* xmi = mrna;
    const size_t WSZ = (size_t)HID * HID;

    for (int l = 0; l < NLAYERS; l++) {
        float* xso = (l == 0) ? xs0 : xs1;
        float* xmo = (l == 0) ? xm0 : xm1;

        // ---- mRNA side ----
        gather_mean_kernel<<<(NM * 32 + 255) / 256, 256>>>(offMd, lstMd, xsi, aggm, NM);
        unsigned gm = (NM + 63) / 64;
        gemm_k128<<<gm, 256>>>(xmi,  sWr + l * WSZ, macc, NM, nullptr, 0);
        gemm_k128<<<gm, 256>>>(aggm, sWl + l * WSZ, macc, NM, sbl + l * HID, FLAG_ACC);
        gemm_k128<<<gm, 256>>>(xmi,  gFW + l * WSZ, xw,   NM, nullptr, 0);
        gemm_k128<<<gm, 256>>>(xmi,  gRW + l * WSZ, xw2,  NM, nullptr, 0);
        gather_gcn_kernel<<<(NM * 32 + 255) / 256, 256>>>(offF, lstF, xw,  dF, macc, NM);
        gather_gcn_kernel<<<(NM * 32 + 255) / 256, 256>>>(offR, lstR, xw2, dR, macc, NM);
        {
            size_t n4 = (size_t)NM * (HID / 4);
            finalize_m_kernel<<<(unsigned)((n4 + 255) / 256), 256>>>(gFb + l * HID, gRb + l * HID, xmo);
        }

        // ---- sRNA side (uses OLD x_m) ----
        gather_mean_kernel<<<(NS * 32 + 255) / 256, 256>>>(offSs, lstSs, xmi, aggs, NS);
        unsigned gs = (NS + 63) / 64;
        gemm_k128<<<gs, 256>>>(xsi,  rWr + l * WSZ, xso, NS, nullptr, 0);
        gemm_k128<<<gs, 256>>>(aggs, rWl + l * WSZ, xso, NS, rbl + l * HID, FLAG_ACC | FLAG_RELU);

        xsi = xso;
        xmi = xmo;
    }

    {
        long long th = (long long)Elbl * 32;
        classify_kernel<<<(unsigned)((th + 255) / 256), 256>>>(lbl_src, lbl_dst, xsi, xmi, (float*)d_out, Elbl);
    }
}

// round 3
// speedup vs baseline: 1.4854x; 1.1199x over previous
#include <cuda_runtime.h>
#include <cstddef>

#define HID 128
#define NS  20000
#define NM  100000
#define ES2M 1000000
#define EM2M 2000000
#define NLAYERS 2

#define FLAG_ACC  1
#define FLAG_RELU 2

// ---------------- scratch (static __device__, no allocation) ----------------
__device__ __align__(16) float g_xs0[NS * HID];
__device__ __align__(16) float g_xs1[NS * HID];
__device__ __align__(16) float g_xm0[NM * HID];
__device__ __align__(16) float g_xm1[NM * HID];
__device__ __align__(16) float g_aggm[NM * HID];
__device__ __align__(16) float g_aggs[NS * HID];
__device__ __align__(16) float g_macc[NM * HID];
__device__ __align__(16) float g_xw [NM * HID];
__device__ __align__(16) float g_xw2[NM * HID];
__device__ float g_dF [NM];   // rsqrt(deg_fwd+1)
__device__ float g_dR [NM];   // rsqrt(deg_rev+1)

// CSR scratch
__device__ int g_cntMd[NM];
__device__ int g_cntSs[NS];
__device__ int g_cntF [NM];
__device__ int g_cntR [NM];
__device__ int g_offMd[NM + 1];
__device__ int g_offSs[NS + 1];
__device__ int g_offF [NM + 1];
__device__ int g_offR [NM + 1];
__device__ int g_curMd[NM];
__device__ int g_curSs[NS];
__device__ int g_curF [NM];
__device__ int g_curR [NM];
__device__ int g_lstMd[ES2M];
__device__ int g_lstSs[ES2M];
__device__ int g_lstF [EM2M];
__device__ int g_lstR [EM2M];
__device__ int g_bsum[4][128];

// ---------------- f32x2 helpers ----------------
__device__ __forceinline__ unsigned long long pack2(float x) {
    unsigned long long r;
    asm("mov.b64 %0, {%1, %1};" : "=l"(r) : "f"(x));
    return r;
}
__device__ __forceinline__ void fma2(unsigned long long& d,
                                     unsigned long long a, unsigned long long b) {
    asm("fma.rn.f32x2 %0, %1, %2, %0;" : "+l"(d) : "l"(a), "l"(b));
}

// ---------------- CSR build ----------------
__global__ void zero_counts_kernel() {
    int i = blockIdx.x * blockDim.x + threadIdx.x;
    if (i < NM) { g_cntMd[i] = 0; g_cntF[i] = 0; g_cntR[i] = 0; }
    if (i < NS) { g_cntSs[i] = 0; }
}

__global__ void hist_s2m_kernel(const int* __restrict__ src, const int* __restrict__ dst, int E) {
    int e = blockIdx.x * blockDim.x + threadIdx.x;
    if (e >= E) return;
    atomicAdd(&g_cntMd[dst[e]], 1);
    atomicAdd(&g_cntSs[src[e]], 1);
}

__global__ void hist_m2m_kernel(const int* __restrict__ src, const int* __restrict__ dst, int E) {
    int e = blockIdx.x * blockDim.x + threadIdx.x;
    if (e >= E) return;
    atomicAdd(&g_cntF[dst[e]], 1);
    atomicAdd(&g_cntR[src[e]], 1);
}

__device__ __forceinline__ void sel_arrays(int arr, const int*& cnt, int*& off, int*& cur, int& n) {
    switch (arr) {
        case 0: cnt = g_cntMd; off = g_offMd; cur = g_curMd; n = NM; break;
        case 1: cnt = g_cntSs; off = g_offSs; cur = g_curSs; n = NS; break;
        case 2: cnt = g_cntF;  off = g_offF;  cur = g_curF;  n = NM; break;
        default: cnt = g_cntR; off = g_offR;  cur = g_curR;  n = NM; break;
    }
}

// phase 1: per-block (1024 elems) exclusive scan, save block totals
__global__ void __launch_bounds__(1024) scan_partial_kernel() {
    const int* cnt; int* off; int* cur; int n;
    sel_arrays(blockIdx.y, cnt, off, cur, n);
    __shared__ int warpsums[32];
    int tid = threadIdx.x, lane = tid & 31, wid = tid >> 5;
    int i = blockIdx.x * 1024 + tid;
    int v = (i < n) ? cnt[i] : 0;
    int x = v;
#pragma unroll
    for (int o = 1; o < 32; o <<= 1) {
        int t = __shfl_up_sync(0xffffffffu, x, o);
        if (lane >= o) x += t;
    }
    if (lane == 31) warpsums[wid] = x;
    __syncthreads();
    if (wid == 0) {
        int w = warpsums[lane];
#pragma unroll
        for (int o = 1; o < 32; o <<= 1) {
            int t = __shfl_up_sync(0xffffffffu, w, o);
            if (lane >= o) w += t;
        }
        warpsums[lane] = w;
    }
    __syncthreads();
    int excl = x - v + (wid ? warpsums[wid - 1] : 0);
    if (i < n) { off[i] = excl; cur[i] = excl; }
    if (tid == 1023) g_bsum[blockIdx.y][blockIdx.x] = excl + v;
}

// phase 2: add prefix of block totals; last block writes off[n]
__global__ void __launch_bounds__(1024) scan_fix_kernel() {
    const int* cnt; int* off; int* cur; int n;
    sel_arrays(blockIdx.y, cnt, off, cur, n);
    __shared__ int sbase;
    int tid = threadIdx.x;
    if (tid < 32) {
        int s = 0;
        for (int j = tid; j < (int)blockIdx.x; j += 32) s += g_bsum[blockIdx.y][j];
#pragma unroll
        for (int o = 16; o > 0; o >>= 1) s += __shfl_xor_sync(0xffffffffu, s, o);
        if (tid == 0) sbase = s;
    }
    __syncthreads();
    int b = sbase;
    int i = blockIdx.x * 1024 + tid;
    if (i < n) { off[i] += b; cur[i] += b; }
    if (blockIdx.x == gridDim.x - 1 && tid == 0)
        off[n] = b + g_bsum[blockIdx.y][blockIdx.x];
}

__global__ void fill_s2m_kernel(const int* __restrict__ src, const int* __restrict__ dst, int E) {
    int e = blockIdx.x * blockDim.x + threadIdx.x;
    if (e >= E) return;
    int s = src[e], d = dst[e];
    g_lstMd[atomicAdd(&g_curMd[d], 1)] = s;
    g_lstSs[atomicAdd(&g_curSs[s], 1)] = d;
}

__global__ void fill_m2m_kernel(const int* __restrict__ src, const int* __restrict__ dst, int E) {
    int e = blockIdx.x * blockDim.x + threadIdx.x;
    if (e >= E) return;
    int s = src[e], d = dst[e];
    g_lstF[atomicAdd(&g_curF[d], 1)] = s;
    g_lstR[atomicAdd(&g_curR[s], 1)] = d;
}

__global__ void deg_kernel() {
    int i = blockIdx.x * blockDim.x + threadIdx.x;
    if (i < NM) {
        g_dF[i] = rsqrtf((float)g_cntF[i] + 1.0f);
        g_dR[i] = rsqrtf((float)g_cntR[i] + 1.0f);
    }
}

// ---------------- gathers (warp per dst row, no atomics) ----------------
__global__ void __launch_bounds__(256) gather_mean_kernel(
    const int* __restrict__ off, const int* __restrict__ lst,
    const float* __restrict__ X, float* __restrict__ OUT, int n)
{
    int w = (blockIdx.x * blockDim.x + threadIdx.x) >> 5;
    if (w >= n) return;
    int lane = threadIdx.x & 31;
    int s = off[w], e = off[w + 1];
    float4 a0 = make_float4(0.f, 0.f, 0.f, 0.f);
    float4 a1 = make_float4(0.f, 0.f, 0.f, 0.f);
    int i = s;
    for (; i + 1 < e; i += 2) {
        int p0 = lst[i], p1 = lst[i + 1];
        float4 v0 = *reinterpret_cast<const float4*>(&X[(size_t)p0 * HID + lane * 4]);
        float4 v1 = *reinterpret_cast<const float4*>(&X[(size_t)p1 * HID + lane * 4]);
        a0.x += v0.x; a0.y += v0.y; a0.z += v0.z; a0.w += v0.w;
        a1.x += v1.x; a1.y += v1.y; a1.z += v1.z; a1.w += v1.w;
    }
    if (i < e) {
        int p0 = lst[i];
        float4 v0 = *reinterpret_cast<const float4*>(&X[(size_t)p0 * HID + lane * 4]);
        a0.x += v0.x; a0.y += v0.y; a0.z += v0.z; a0.w += v0.w;
    }
    float inv = 1.0f / fmaxf((float)(e - s), 1.0f);
    float4 o;
    o.x = (a0.x + a1.x) * inv; o.y = (a0.y + a1.y) * inv;
    o.z = (a0.z + a1.z) * inv; o.w = (a0.w + a1.w) * inv;
    *reinterpret_cast<float4*>(&OUT[(size_t)w * HID + lane * 4]) = o;
}

// fused GCN fwd+rev gather + self-loops + biases + relu -> out (per row, one write)
__global__ void __launch_bounds__(256) gcn_fused_kernel(
    const float* __restrict__ bF, const float* __restrict__ bR,
    float* __restrict__ out)
{
    int w = (blockIdx.x * blockDim.x + threadIdx.x) >> 5;
    if (w >= NM) return;
    int lane = threadIdx.x & 31;
    size_t ro = (size_t)w * HID + lane * 4;

    // forward gather over lstF on xw, weights dF
    float4 aF = make_float4(0.f, 0.f, 0.f, 0.f);
    {
        int s = g_offF[w], e = g_offF[w + 1];
        float4 t1 = make_float4(0.f, 0.f, 0.f, 0.f);
        int i = s;
        for (; i + 1 < e; i += 2) {
            int p0 = g_lstF[i], p1 = g_lstF[i + 1];
            float w0 = g_dF[p0], w1 = g_dF[p1];
            float4 v0 = *reinterpret_cast<const float4*>(&g_xw[(size_t)p0 * HID + lane * 4]);
            float4 v1 = *reinterpret_cast<const float4*>(&g_xw[(size_t)p1 * HID + lane * 4]);
            aF.x += w0 * v0.x; aF.y += w0 * v0.y; aF.z += w0 * v0.z; aF.w += w0 * v0.w;
            t1.x += w1 * v1.x; t1.y += w1 * v1.y; t1.z += w1 * v1.z; t1.w += w1 * v1.w;
        }
        if (i < e) {
            int p0 = g_lstF[i];
            float w0 = g_dF[p0];
            float4 v0 = *reinterpret_cast<const float4*>(&g_xw[(size_t)p0 * HID + lane * 4]);
            aF.x += w0 * v0.x; aF.y += w0 * v0.y; aF.z += w0 * v0.z; aF.w += w0 * v0.w;
        }
        aF.x += t1.x; aF.y += t1.y; aF.z += t1.z; aF.w += t1.w;
    }
    // reverse gather over lstR on xw2, weights dR
    float4 aR = make_float4(0.f, 0.f, 0.f, 0.f);
    {
        int s = g_offR[w], e = g_offR[w + 1];
        float4 t1 = make_float4(0.f, 0.f, 0.f, 0.f);
        int i = s;
        for (; i + 1 < e; i += 2) {
            int p0 = g_lstR[i], p1 = g_lstR[i + 1];
            float w0 = g_dR[p0], w1 = g_dR[p1];
            float4 v0 = *reinterpret_cast<const float4*>(&g_xw2[(size_t)p0 * HID + lane * 4]);
            float4 v1 = *reinterpret_cast<const float4*>(&g_xw2[(size_t)p1 * HID + lane * 4]);
            aR.x += w0 * v0.x; aR.y += w0 * v0.y; aR.z += w0 * v0.z; aR.w += w0 * v0.w;
            t1.x += w1 * v1.x; t1.y += w1 * v1.y; t1.z += w1 * v1.z; t1.w += w1 * v1.w;
        }
        if (i < e) {
            int p0 = g_lstR[i];
            float w0 = g_dR[p0];
            float4 v0 = *reinterpret_cast<const float4*>(&g_xw2[(size_t)p0 * HID + lane * 4]);
            aR.x += w0 * v0.x; aR.y += w0 * v0.y; aR.z += w0 * v0.z; aR.w += w0 * v0.w;
        }
        aR.x += t1.x; aR.y += t1.y; aR.z += t1.z; aR.w += t1.w;
    }

    float f = g_dF[w], r = g_dR[w];
    float f2 = f * f, r2 = r * r;
    float4 m  = *reinterpret_cast<const float4*>(&g_macc[ro]);
    float4 xv = *reinterpret_cast<const float4*>(&g_xw[ro]);
    float4 x2 = *reinterpret_cast<const float4*>(&g_xw2[ro]);
    float4 bf = reinterpret_cast<const float4*>(bF)[lane];
    float4 br = reinterpret_cast<const float4*>(bR)[lane];
    float4 o;
    o.x = fmaxf(m.x + f * aF.x + f2 * xv.x + bf.x + r * aR.x + r2 * x2.x + br.x, 0.f);
    o.y = fmaxf(m.y + f * aF.y + f2 * xv.y + bf.y + r * aR.y + r2 * x2.y + br.y, 0.f);
    o.z = fmaxf(m.z + f * aF.z + f2 * xv.z + bf.z + r * aR.z + r2 * x2.z + br.z, 0.f);
    o.w = fmaxf(m.w + f * aF.w + f2 * xv.w + bf.w + r * aR.w + r2 * x2.w + br.w, 0.f);
    *reinterpret_cast<float4*>(&out[ro]) = o;
}

// ---------------- GEMM (packed f32x2): D[M,128] (+)= A[M,128]@B[128,128] + bias ----------------
__global__ void __launch_bounds__(256) gemm_k128(
    const float* __restrict__ A, const float* __restrict__ B,
    float* __restrict__ D, int M,
    const float* __restrict__ bias, int flags)
{
    __shared__ float As[64][33];
    __shared__ __align__(16) float Bs[32][128];
    int tid = threadIdx.x;
    int tx = tid & 15;          // 16 col-groups of 8
    int ty = tid >> 4;          // 16 row-groups of 4
    int r0 = blockIdx.x * 64;

    unsigned long long acc2[4][4];
#pragma unroll
    for (int i = 0; i < 4; i++)
#pragma unroll
        for (int j = 0; j < 4; j++) acc2[i][j] = 0ull;

    for (int k0 = 0; k0 < 128; k0 += 32) {
#pragma unroll
        for (int it = 0; it < 2; it++) {
            int idx = tid + it * 256;        // 0..511
            int row = idx >> 3, kq = idx & 7;
            float4 v = make_float4(0.f, 0.f, 0.f, 0.f);
            if (r0 + row < M)
                v = *reinterpret_cast<const float4*>(&A[(size_t)(r0 + row) * 128 + k0 + kq * 4]);
            As[row][kq * 4 + 0] = v.x;
            As[row][kq * 4 + 1] = v.y;
            As[row][kq * 4 + 2] = v.z;
            As[row][kq * 4 + 3] = v.w;
        }
#pragma unroll
        for (int it = 0; it < 4; it++) {
            int idx = tid + it * 256;        // 0..1023
            int kr = idx >> 5, c4 = idx & 31;
            *reinterpret_cast<float4*>(&Bs[kr][c4 * 4]) =
                *reinterpret_cast<const float4*>(&B[(size_t)(k0 + kr) * 128 + c4 * 4]);
        }
        __syncthreads();
#pragma unroll
        for (int k = 0; k < 32; k++) {
            unsigned long long a2[4];
#pragma unroll
            for (int i = 0; i < 4; i++) a2[i] = pack2(As[ty * 4 + i][k]);
            ulonglong2 bl0 = *reinterpret_cast<const ulonglong2*>(&Bs[k][tx * 8]);
            ulonglong2 bl1 = *reinterpret_cast<const ulonglong2*>(&Bs[k][tx * 8 + 4]);
#pragma unroll
            for (int i = 0; i < 4; i++) {
                fma2(acc2[i][0], a2[i], bl0.x);
                fma2(acc2[i][1], a2[i], bl0.y);
                fma2(acc2[i][2], a2[i], bl1.x);
                fma2(acc2[i][3], a2[i], bl1.y);
            }
        }
        __syncthreads();
    }

    float bv[8];
    if (bias) {
        float4 bb0 = *reinterpret_cast<const float4*>(&bias[tx * 8]);
        float4 bb1 = *reinterpret_cast<const float4*>(&bias[tx * 8 + 4]);
        bv[0]=bb0.x; bv[1]=bb0.y; bv[2]=bb0.z; bv[3]=bb0.w;
        bv[4]=bb1.x; bv[5]=bb1.y; bv[6]=bb1.z; bv[7]=bb1.w;
    } else {
#pragma unroll
        for (int j = 0; j < 8; j++) bv[j] = 0.f;
    }

#pragma unroll
    for (int i = 0; i < 4; i++) {
        int row = r0 + ty * 4 + i;
        if (row >= M) continue;
        float o[8];
#pragma unroll
        for (int j = 0; j < 4; j++) {
            float2 p = *reinterpret_cast<float2*>(&acc2[i][j]);
            o[2 * j]     = p.x + bv[2 * j];
            o[2 * j + 1] = p.y + bv[2 * j + 1];
        }
        float* dp = &D[(size_t)row * 128 + tx * 8];
        if (flags & FLAG_ACC) {
            float4 d0 = *reinterpret_cast<const float4*>(dp);
            float4 d1 = *reinterpret_cast<const float4*>(dp + 4);
            o[0]+=d0.x; o[1]+=d0.y; o[2]+=d0.z; o[3]+=d0.w;
            o[4]+=d1.x; o[5]+=d1.y; o[6]+=d1.z; o[7]+=d1.w;
        }
        if (flags & FLAG_RELU) {
#pragma unroll
            for (int j = 0; j < 8; j++) o[j] = fmaxf(o[j], 0.f);
        }
        *reinterpret_cast<float4*>(dp)     = make_float4(o[0], o[1], o[2], o[3]);
        *reinterpret_cast<float4*>(dp + 4) = make_float4(o[4], o[5], o[6], o[7]);
    }
}

// ---------------- classifier ----------------
__global__ void __launch_bounds__(256) classify_kernel(
    const int* __restrict__ ls, const int* __restrict__ ld,
    const float* __restrict__ XS, const float* __restrict__ XM,
    float* __restrict__ out, int E)
{
    long long t = (long long)blockIdx.x * blockDim.x + threadIdx.x;
    int e = (int)(t >> 5);
    if (e >= E) return;
    int lane = (int)(t & 31);
    int s = ls[e], d = ld[e];
    float4 a = *reinterpret_cast<const float4*>(&XS[(size_t)s * HID + lane * 4]);
    float4 b = *reinterpret_cast<const float4*>(&XM[(size_t)d * HID + lane * 4]);
    float p = a.x * b.x + a.y * b.y + a.z * b.z + a.w * b.w;
#pragma unroll
    for (int o = 16; o > 0; o >>= 1) p += __shfl_xor_sync(0xffffffffu, p, o);
    if (lane == 0) out[e] = p;
}

// ---------------- host ----------------
extern "C" void kernel_launch(void* const* d_in, const int* in_sizes, int n_in,
                              void* d_out, int out_size)
{
    const int*   s2m_src = (const int*)d_in[0];
    const int*   s2m_dst = (const int*)d_in[1];
    const int*   m2m_src = (const int*)d_in[2];
    const int*   m2m_dst = (const int*)d_in[3];
    const int*   lbl_src = (const int*)d_in[4];
    const int*   lbl_dst = (const int*)d_in[5];
    const float* srna    = (const float*)d_in[6];
    const float* mrna    = (const float*)d_in[7];
    const float* sWl     = (const float*)d_in[8];
    const float* sbl     = (const float*)d_in[9];
    const float* sWr     = (const float*)d_in[10];
    const float* rWl     = (const float*)d_in[11];
    const float* rbl     = (const float*)d_in[12];
    const float* rWr     = (const float*)d_in[13];
    const float* gFW     = (const float*)d_in[14];
    const float* gFb     = (const float*)d_in[15];
    const float* gRW     = (const float*)d_in[16];
    const float* gRb     = (const float*)d_in[17];

    const int Es2m = in_sizes[0];
    const int Em2m = in_sizes[2];
    const int Elbl = in_sizes[4];

    float *xs0, *xs1, *xm0, *xm1, *aggm, *aggs, *macc, *xw, *xw2;
    int *offMd, *offSs, *lstMd, *lstSs;
    cudaGetSymbolAddress((void**)&xs0, g_xs0);
    cudaGetSymbolAddress((void**)&xs1, g_xs1);
    cudaGetSymbolAddress((void**)&xm0, g_xm0);
    cudaGetSymbolAddress((void**)&xm1, g_xm1);
    cudaGetSymbolAddress((void**)&aggm, g_aggm);
    cudaGetSymbolAddress((void**)&aggs, g_aggs);
    cudaGetSymbolAddress((void**)&macc, g_macc);
    cudaGetSymbolAddress((void**)&xw, g_xw);
    cudaGetSymbolAddress((void**)&xw2, g_xw2);
    cudaGetSymbolAddress((void**)&offMd, g_offMd);
    cudaGetSymbolAddress((void**)&offSs, g_offSs);
    cudaGetSymbolAddress((void**)&lstMd, g_lstMd);
    cudaGetSymbolAddress((void**)&lstSs, g_lstSs);

    // ---- CSR build ----
    zero_counts_kernel<<<(NM + 255) / 256, 256>>>();
    hist_s2m_kernel<<<(Es2m + 255) / 256, 256>>>(s2m_src, s2m_dst, Es2m);
    hist_m2m_kernel<<<(Em2m + 255) / 256, 256>>>(m2m_src, m2m_dst, Em2m);
    {
        dim3 g((NM + 1023) / 1024, 4);
        scan_partial_kernel<<<g, 1024>>>();
        scan_fix_kernel<<<g, 1024>>>();
    }
    fill_s2m_kernel<<<(Es2m + 255) / 256, 256>>>(s2m_src, s2m_dst, Es2m);
    fill_m2m_kernel<<<(Em2m + 255) / 256, 256>>>(m2m_src, m2m_dst, Em2m);
    deg_kernel<<<(NM + 255) / 256, 256>>>();

    const float* xsi = srna;
    const float* xmi = mrna;
    const size_t WSZ = (size_t)HID * HID;

    for (int l = 0; l < NLAYERS; l++) {
        float* xso = (l == 0) ? xs0 : xs1;
        float* xmo = (l == 0) ? xm0 : xm1;

        // ---- mRNA side ----
        gather_mean_kernel<<<(NM * 32 + 255) / 256, 256>>>(offMd, lstMd, xsi, aggm, NM);
        unsigned gm = (NM + 63) / 64;
        gemm_k128<<<gm, 256>>>(xmi,  sWr + l * WSZ, macc, NM, nullptr, 0);
        gemm_k128<<<gm, 256>>>(aggm, sWl + l * WSZ, macc, NM, sbl + l * HID, FLAG_ACC);
        gemm_k128<<<gm, 256>>>(xmi,  gFW + l * WSZ, xw,   NM, nullptr, 0);
        gemm_k128<<<gm, 256>>>(xmi,  gRW + l * WSZ, xw2,  NM, nullptr, 0);
        gcn_fused_kernel<<<(NM * 32 + 255) / 256, 256>>>(gFb + l * HID, gRb + l * HID, xmo);

        // ---- sRNA side (uses OLD x_m) ----
        gather_mean_kernel<<<(NS * 32 + 255) / 256, 256>>>(offSs, lstSs, xmi, aggs, NS);
        unsigned gs = (NS + 63) / 64;
        gemm_k128<<<gs, 256>>>(xsi,  rWr + l * WSZ, xso, NS, nullptr, 0);
        gemm_k128<<<gs, 256>>>(aggs, rWl + l * WSZ, xso, NS, rbl + l * HID, FLAG_ACC | FLAG_RELU);

        xsi = xso;
        xmi = xmo;
    }

    {
        long long th = (long long)Elbl * 32;
        classify_kernel<<<(unsigned)((th + 255) / 256), 256>>>(lbl_src, lbl_dst, xsi, xmi, (float*)d_out, Elbl);
    }
}

// round 4
// speedup vs baseline: 2.0144x; 1.3561x over previous
#include <cuda_runtime.h>
#include <cuda_bf16.h>
#include <cstddef>
#include <cstdint>

#define HID 128
#define NS  20000
#define NM  100000
#define NSP 20096
#define NMP 100096
#define ES2M 1000000
#define EM2M 2000000
#define NLAYERS 2

#define FLAG_ACC  1
#define FLAG_RELU 2

#define GEMM_SMEM (2 * 128 * 136 * 2)   // Bh + Bl, bf16, padded pitch 136

// ---------------- scratch (static __device__, no allocation) ----------------
__device__ __align__(16) float g_xs0[NS * HID];
__device__ __align__(16) float g_xs1[NS * HID];
__device__ __align__(16) float g_xm0[NM * HID];
__device__ __align__(16) float g_xm1[NM * HID];
__device__ __align__(16) float g_aggm[NM * HID];
__device__ __align__(16) float g_aggs[NS * HID];
__device__ __align__(16) float g_macc[NM * HID];
__device__ __align__(16) float g_xw [NM * HID];
__device__ __align__(16) float g_xw2[NM * HID];
__device__ float g_dF [NM];
__device__ float g_dR [NM];

// split-bf16 operand buffers
__device__ __align__(16) __nv_bfloat16 g_Amh[NMP * HID];
__device__ __align__(16) __nv_bfloat16 g_Aml[NMP * HID];
__device__ __align__(16) __nv_bfloat16 g_Ash[NSP * HID];
__device__ __align__(16) __nv_bfloat16 g_Asl[NSP * HID];
__device__ __align__(16) __nv_bfloat16 g_Wth[12 * HID * HID];  // transposed [n][k]
__device__ __align__(16) __nv_bfloat16 g_Wtl[12 * HID * HID];

// CSR scratch
__device__ int g_cntMd[NM];
__device__ int g_cntSs[NS];
__device__ int g_cntF [NM];
__device__ int g_cntR [NM];
__device__ int g_offMd[NM + 1];
__device__ int g_offSs[NS + 1];
__device__ int g_offF [NM + 1];
__device__ int g_offR [NM + 1];
__device__ int g_curMd[NM];
__device__ int g_curSs[NS];
__device__ int g_curF [NM];
__device__ int g_curR [NM];
__device__ int g_lstMd[ES2M];
__device__ int g_lstSs[ES2M];
__device__ int g_lstF [EM2M];
__device__ int g_lstR [EM2M];
__device__ int g_bsum[4][128];

// ---------------- CSR build ----------------
__global__ void zero_counts_kernel() {
    int i = blockIdx.x * blockDim.x + threadIdx.x;
    if (i < NM) { g_cntMd[i] = 0; g_cntF[i] = 0; g_cntR[i] = 0; }
    if (i < NS) { g_cntSs[i] = 0; }
}

__global__ void hist_s2m_kernel(const int* __restrict__ src, const int* __restrict__ dst, int E) {
    int e = blockIdx.x * blockDim.x + threadIdx.x;
    if (e >= E) return;
    atomicAdd(&g_cntMd[dst[e]], 1);
    atomicAdd(&g_cntSs[src[e]], 1);
}

__global__ void hist_m2m_kernel(const int* __restrict__ src, const int* __restrict__ dst, int E) {
    int e = blockIdx.x * blockDim.x + threadIdx.x;
    if (e >= E) return;
    atomicAdd(&g_cntF[dst[e]], 1);
    atomicAdd(&g_cntR[src[e]], 1);
}

__device__ __forceinline__ void sel_arrays(int arr, const int*& cnt, int*& off, int*& cur, int& n) {
    switch (arr) {
        case 0: cnt = g_cntMd; off = g_offMd; cur = g_curMd; n = NM; break;
        case 1: cnt = g_cntSs; off = g_offSs; cur = g_curSs; n = NS; break;
        case 2: cnt = g_cntF;  off = g_offF;  cur = g_curF;  n = NM; break;
        default: cnt = g_cntR; off = g_offR;  cur = g_curR;  n = NM; break;
    }
}

__global__ void __launch_bounds__(1024) scan_partial_kernel() {
    const int* cnt; int* off; int* cur; int n;
    sel_arrays(blockIdx.y, cnt, off, cur, n);
    __shared__ int warpsums[32];
    int tid = threadIdx.x, lane = tid & 31, wid = tid >> 5;
    int i = blockIdx.x * 1024 + tid;
    int v = (i < n) ? cnt[i] : 0;
    int x = v;
#pragma unroll
    for (int o = 1; o < 32; o <<= 1) {
        int t = __shfl_up_sync(0xffffffffu, x, o);
        if (lane >= o) x += t;
    }
    if (lane == 31) warpsums[wid] = x;
    __syncthreads();
    if (wid == 0) {
        int w = warpsums[lane];
#pragma unroll
        for (int o = 1; o < 32; o <<= 1) {
            int t = __shfl_up_sync(0xffffffffu, w, o);
            if (lane >= o) w += t;
        }
        warpsums[lane] = w;
    }
    __syncthreads();
    int excl = x - v + (wid ? warpsums[wid - 1] : 0);
    if (i < n) { off[i] = excl; cur[i] = excl; }
    if (tid == 1023) g_bsum[blockIdx.y][blockIdx.x] = excl + v;
}

__global__ void __launch_bounds__(1024) scan_fix_kernel() {
    const int* cnt; int* off; int* cur; int n;
    sel_arrays(blockIdx.y, cnt, off, cur, n);
    __shared__ int sbase;
    int tid = threadIdx.x;
    if (tid < 32) {
        int s = 0;
        for (int j = tid; j < (int)blockIdx.x; j += 32) s += g_bsum[blockIdx.y][j];
#pragma unroll
        for (int o = 16; o > 0; o >>= 1) s += __shfl_xor_sync(0xffffffffu, s, o);
        if (tid == 0) sbase = s;
    }
    __syncthreads();
    int b = sbase;
    int i = blockIdx.x * 1024 + tid;
    if (i < n) { off[i] += b; cur[i] += b; }
    if (blockIdx.x == gridDim.x - 1 && tid == 0)
        off[n] = b + g_bsum[blockIdx.y][blockIdx.x];
}

__global__ void fill_s2m_kernel(const int* __restrict__ src, const int* __restrict__ dst, int E) {
    int e = blockIdx.x * blockDim.x + threadIdx.x;
    if (e >= E) return;
    int s = src[e], d = dst[e];
    g_lstMd[atomicAdd(&g_curMd[d], 1)] = s;
    g_lstSs[atomicAdd(&g_curSs[s], 1)] = d;
}

__global__ void fill_m2m_kernel(const int* __restrict__ src, const int* __restrict__ dst, int E) {
    int e = blockIdx.x * blockDim.x + threadIdx.x;
    if (e >= E) return;
    int s = src[e], d = dst[e];
    g_lstF[atomicAdd(&g_curF[d], 1)] = s;
    g_lstR[atomicAdd(&g_curR[s], 1)] = d;
}

__global__ void deg_kernel() {
    int i = blockIdx.x * blockDim.x + threadIdx.x;
    if (i < NM) {
        g_dF[i] = rsqrtf((float)g_cntF[i] + 1.0f);
        g_dR[i] = rsqrtf((float)g_cntR[i] + 1.0f);
    }
}

// ---------------- split conversions ----------------
__global__ void __launch_bounds__(256) split_kernel(
    const float* __restrict__ X,
    __nv_bfloat16* __restrict__ hi, __nv_bfloat16* __restrict__ lo, int n4)
{
    int i = blockIdx.x * blockDim.x + threadIdx.x;
    if (i >= n4) return;
    float4 v = reinterpret_cast<const float4*>(X)[i];
    __nv_bfloat16 h0 = __float2bfloat16(v.x);
    __nv_bfloat16 h1 = __float2bfloat16(v.y);
    __nv_bfloat16 h2 = __float2bfloat16(v.z);
    __nv_bfloat16 h3 = __float2bfloat16(v.w);
    __nv_bfloat16 l0 = __float2bfloat16(v.x - __bfloat162float(h0));
    __nv_bfloat16 l1 = __float2bfloat16(v.y - __bfloat162float(h1));
    __nv_bfloat16 l2 = __float2bfloat16(v.z - __bfloat162float(h2));
    __nv_bfloat16 l3 = __float2bfloat16(v.w - __bfloat162float(h3));
    __nv_bfloat162 ph0 = __nv_bfloat162(h0, h1), ph1 = __nv_bfloat162(h2, h3);
    __nv_bfloat162 pl0 = __nv_bfloat162(l0, l1), pl1 = __nv_bfloat162(l2, l3);
    uint2 uh, ul;
    uh.x = *reinterpret_cast<uint32_t*>(&ph0); uh.y = *reinterpret_cast<uint32_t*>(&ph1);
    ul.x = *reinterpret_cast<uint32_t*>(&pl0); ul.y = *reinterpret_cast<uint32_t*>(&pl1);
    reinterpret_cast<uint2*>(hi)[i] = uh;
    reinterpret_cast<uint2*>(lo)[i] = ul;
}

// weight: W[k][n] (row-major KxN) -> Bt[n][k] split
__global__ void wsplit_kernel(const float* __restrict__ W,
                              __nv_bfloat16* __restrict__ oh,
                              __nv_bfloat16* __restrict__ ol)
{
    int i = blockIdx.x * blockDim.x + threadIdx.x;
    if (i >= HID * HID) return;
    int k = i >> 7, n = i & 127;
    float x = W[i];
    __nv_bfloat16 h = __float2bfloat16(x);
    oh[n * 128 + k] = h;
    ol[n * 128 + k] = __float2bfloat16(x - __bfloat162float(h));
}

// ---------------- tensor-core GEMM (split bf16, 3-product fp32 emulation) ----------------
__device__ __forceinline__ void mma16816(float* c,
    uint32_t a0, uint32_t a1, uint32_t a2, uint32_t a3,
    uint32_t b0, uint32_t b1)
{
    asm volatile("mma.sync.aligned.m16n8k16.row.col.f32.bf16.bf16.f32 "
        "{%0,%1,%2,%3}, {%4,%5,%6,%7}, {%8,%9}, {%0,%1,%2,%3};"
        : "+f"(c[0]), "+f"(c[1]), "+f"(c[2]), "+f"(c[3])
        : "r"(a0), "r"(a1), "r"(a2), "r"(a3), "r"(b0), "r"(b1));
}

// D[M,128] (+)= A[M,128] @ W[128,128] (+bias)(relu). A given as hi/lo bf16 [Mpad,128].
// Bt given as hi/lo bf16 [128n][128k] (transposed weight).
__global__ void __launch_bounds__(256) gemm_bf16_split(
    const __nv_bfloat16* __restrict__ Ahi, const __nv_bfloat16* __restrict__ Alo,
    const __nv_bfloat16* __restrict__ Bthi, const __nv_bfloat16* __restrict__ Btlo,
    float* __restrict__ D, int M, const float* __restrict__ bias, int flags)
{
    extern __shared__ __nv_bfloat16 sh[];
    __nv_bfloat16* Bh = sh;                 // [128][136]
    __nv_bfloat16* Bl = sh + 128 * 136;
    int tid = threadIdx.x;
    for (int i = tid; i < 128 * 64; i += 256) {     // 64 b32 per row
        int r = i >> 6, c = i & 63;
        reinterpret_cast<uint32_t*>(Bh + r * 136)[c] = reinterpret_cast<const uint32_t*>(Bthi)[i];
        reinterpret_cast<uint32_t*>(Bl + r * 136)[c] = reinterpret_cast<const uint32_t*>(Btlo)[i];
    }
    __syncthreads();

    int warp = tid >> 5, lane = tid & 31;
    int g = lane >> 2, t4 = lane & 3;
    int m0 = blockIdx.x * 128 + warp * 16;
    const uint32_t* ah = reinterpret_cast<const uint32_t*>(Ahi) + (size_t)m0 * 64;
    const uint32_t* al = reinterpret_cast<const uint32_t*>(Alo) + (size_t)m0 * 64;

    float acc[16][4];
#pragma unroll
    for (int nf = 0; nf < 16; nf++)
#pragma unroll
        for (int j = 0; j < 4; j++) acc[nf][j] = 0.f;

#pragma unroll 2
    for (int k0 = 0; k0 < 8; k0++) {
        int kb = k0 * 8;
        uint32_t a0h = ah[g * 64 + kb + t4];
        uint32_t a1h = ah[(g + 8) * 64 + kb + t4];
        uint32_t a2h = ah[g * 64 + kb + t4 + 4];
        uint32_t a3h = ah[(g + 8) * 64 + kb + t4 + 4];
        uint32_t a0l = al[g * 64 + kb + t4];
        uint32_t a1l = al[(g + 8) * 64 + kb + t4];
        uint32_t a2l = al[g * 64 + kb + t4 + 4];
        uint32_t a3l = al[(g + 8) * 64 + kb + t4 + 4];
#pragma unroll
        for (int nf = 0; nf < 16; nf++) {
            int n = nf * 8 + g;
            const uint32_t* bh = reinterpret_cast<const uint32_t*>(Bh + n * 136);
            const uint32_t* bl = reinterpret_cast<const uint32_t*>(Bl + n * 136);
            uint32_t b0h = bh[kb + t4], b1h = bh[kb + t4 + 4];
            uint32_t b0l = bl[kb + t4], b1l = bl[kb + t4 + 4];
            mma16816(acc[nf], a0h, a1h, a2h, a3h, b0h, b1h);
            mma16816(acc[nf], a0h, a1h, a2h, a3h, b0l, b1l);
            mma16816(acc[nf], a0l, a1l, a2l, a3l, b0h, b1h);
        }
    }

    int r0 = m0 + g, r1 = m0 + g + 8;
#pragma unroll
    for (int nf = 0; nf < 16; nf++) {
        int c = nf * 8 + t4 * 2;
        float bx = 0.f, by = 0.f;
        if (bias) { float2 bv = *reinterpret_cast<const float2*>(&bias[c]); bx = bv.x; by = bv.y; }
        if (r0 < M) {
            float2* p = reinterpret_cast<float2*>(&D[(size_t)r0 * 128 + c]);
            float2 o = make_float2(acc[nf][0] + bx, acc[nf][1] + by);
            if (flags & FLAG_ACC) { float2 d = *p; o.x += d.x; o.y += d.y; }
            if (flags & FLAG_RELU) { o.x = fmaxf(o.x, 0.f); o.y = fmaxf(o.y, 0.f); }
            *p = o;
        }
        if (r1 < M) {
            float2* p = reinterpret_cast<float2*>(&D[(size_t)r1 * 128 + c]);
            float2 o = make_float2(acc[nf][2] + bx, acc[nf][3] + by);
            if (flags & FLAG_ACC) { float2 d = *p; o.x += d.x; o.y += d.y; }
            if (flags & FLAG_RELU) { o.x = fmaxf(o.x, 0.f); o.y = fmaxf(o.y, 0.f); }
            *p = o;
        }
    }
}

// ---------------- gathers (warp per dst row, no atomics) ----------------
__global__ void __launch_bounds__(256) gather_mean_kernel(
    const int* __restrict__ off, const int* __restrict__ lst,
    const float* __restrict__ X, float* __restrict__ OUT, int n)
{
    int w = (blockIdx.x * blockDim.x + threadIdx.x) >> 5;
    if (w >= n) return;
    int lane = threadIdx.x & 31;
    int s = off[w], e = off[w + 1];
    float4 a0 = make_float4(0.f, 0.f, 0.f, 0.f);
    float4 a1 = make_float4(0.f, 0.f, 0.f, 0.f);
    int i = s;
    for (; i + 1 < e; i += 2) {
        int p0 = lst[i], p1 = lst[i + 1];
        float4 v0 = *reinterpret_cast<const float4*>(&X[(size_t)p0 * HID + lane * 4]);
        float4 v1 = *reinterpret_cast<const float4*>(&X[(size_t)p1 * HID + lane * 4]);
        a0.x += v0.x; a0.y += v0.y; a0.z += v0.z; a0.w += v0.w;
        a1.x += v1.x; a1.y += v1.y; a1.z += v1.z; a1.w += v1.w;
    }
    if (i < e) {
        int p0 = lst[i];
        float4 v0 = *reinterpret_cast<const float4*>(&X[(size_t)p0 * HID + lane * 4]);
        a0.x += v0.x; a0.y += v0.y; a0.z += v0.z; a0.w += v0.w;
    }
    float inv = 1.0f / fmaxf((float)(e - s), 1.0f);
    float4 o;
    o.x = (a0.x + a1.x) * inv; o.y = (a0.y + a1.y) * inv;
    o.z = (a0.z + a1.z) * inv; o.w = (a0.w + a1.w) * inv;
    *reinterpret_cast<float4*>(&OUT[(size_t)w * HID + lane * 4]) = o;
}

// fused GCN fwd+rev gather + self-loops + biases + relu -> out
__global__ void __launch_bounds__(256) gcn_fused_kernel(
    const float* __restrict__ bF, const float* __restrict__ bR,
    float* __restrict__ out)
{
    int w = (blockIdx.x * blockDim.x + threadIdx.x) >> 5;
    if (w >= NM) return;
    int lane = threadIdx.x & 31;
    size_t ro = (size_t)w * HID + lane * 4;

    float4 aF = make_float4(0.f, 0.f, 0.f, 0.f);
    {
        int s = g_offF[w], e = g_offF[w + 1];
        float4 t1 = make_float4(0.f, 0.f, 0.f, 0.f);
        int i = s;
        for (; i + 1 < e; i += 2) {
            int p0 = g_lstF[i], p1 = g_lstF[i + 1];
            float w0 = g_dF[p0], w1 = g_dF[p1];
            float4 v0 = *reinterpret_cast<const float4*>(&g_xw[(size_t)p0 * HID + lane * 4]);
            float4 v1 = *reinterpret_cast<const float4*>(&g_xw[(size_t)p1 * HID + lane * 4]);
            aF.x += w0 * v0.x; aF.y += w0 * v0.y; aF.z += w0 * v0.z; aF.w += w0 * v0.w;
            t1.x += w1 * v1.x; t1.y += w1 * v1.y; t1.z += w1 * v1.z; t1.w += w1 * v1.w;
        }
        if (i < e) {
            int p0 = g_lstF[i];
            float w0 = g_dF[p0];
            float4 v0 = *reinterpret_cast<const float4*>(&g_xw[(size_t)p0 * HID + lane * 4]);
            aF.x += w0 * v0.x; aF.y += w0 * v0.y; aF.z += w0 * v0.z; aF.w += w0 * v0.w;
        }
        aF.x += t1.x; aF.y += t1.y; aF.z += t1.z; aF.w += t1.w;
    }
    float4 aR = make_float4(0.f, 0.f, 0.f, 0.f);
    {
        int s = g_offR[w], e = g_offR[w + 1];
        float4 t1 = make_float4(0.f, 0.f, 0.f, 0.f);
        int i = s;
        for (; i + 1 < e; i += 2) {
            int p0 = g_lstR[i], p1 = g_lstR[i + 1];
            float w0 = g_dR[p0], w1 = g_dR[p1];
            float4 v0 = *reinterpret_cast<const float4*>(&g_xw2[(size_t)p0 * HID + lane * 4]);
            float4 v1 = *reinterpret_cast<const float4*>(&g_xw2[(size_t)p1 * HID + lane * 4]);
            aR.x += w0 * v0.x; aR.y += w0 * v0.y; aR.z += w0 * v0.z; aR.w += w0 * v0.w;
            t1.x += w1 * v1.x; t1.y += w1 * v1.y; t1.z += w1 * v1.z; t1.w += w1 * v1.w;
        }
        if (i < e) {
            int p0 = g_lstR[i];
            float w0 = g_dR[p0];
            float4 v0 = *reinterpret_cast<const float4*>(&g_xw2[(size_t)p0 * HID + lane * 4]);
            aR.x += w0 * v0.x; aR.y += w0 * v0.y; aR.z += w0 * v0.z; aR.w += w0 * v0.w;
        }
        aR.x += t1.x; aR.y += t1.y; aR.z += t1.z; aR.w += t1.w;
    }

    float f = g_dF[w], r = g_dR[w];
    float f2 = f * f, r2 = r * r;
    float4 m  = *reinterpret_cast<const float4*>(&g_macc[ro]);
    float4 xv = *reinterpret_cast<const float4*>(&g_xw[ro]);
    float4 x2 = *reinterpret_cast<const float4*>(&g_xw2[ro]);
    float4 bf = reinterpret_cast<const float4*>(bF)[lane];
    float4 br = reinterpret_cast<const float4*>(bR)[lane];
    float4 o;
    o.x = fmaxf(m.x + f * aF.x + f2 * xv.x + bf.x + r * aR.x + r2 * x2.x + br.x, 0.f);
    o.y = fmaxf(m.y + f * aF.y + f2 * xv.y + bf.y + r * aR.y + r2 * x2.y + br.y, 0.f);
    o.z = fmaxf(m.z + f * aF.z + f2 * xv.z + bf.z + r * aR.z + r2 * x2.z + br.z, 0.f);
    o.w = fmaxf(m.w + f * aF.w + f2 * xv.w + bf.w + r * aR.w + r2 * x2.w + br.w, 0.f);
    *reinterpret_cast<float4*>(&out[ro]) = o;
}

// ---------------- classifier ----------------
__global__ void __launch_bounds__(256) classify_kernel(
    const int* __restrict__ ls, const int* __restrict__ ld,
    const float* __restrict__ XS, const float* __restrict__ XM,
    float* __restrict__ out, int E)
{
    long long t = (long long)blockIdx.x * blockDim.x + threadIdx.x;
    int e = (int)(t >> 5);
    if (e >= E) return;
    int lane = (int)(t & 31);
    int s = ls[e], d = ld[e];
    float4 a = *reinterpret_cast<const float4*>(&XS[(size_t)s * HID + lane * 4]);
    float4 b = *reinterpret_cast<const float4*>(&XM[(size_t)d * HID + lane * 4]);
    float p = a.x * b.x + a.y * b.y + a.z * b.z + a.w * b.w;
#pragma unroll
    for (int o = 16; o > 0; o >>= 1) p += __shfl_xor_sync(0xffffffffu, p, o);
    if (lane == 0) out[e] = p;
}

// ---------------- host ----------------
extern "C" void kernel_launch(void* const* d_in, const int* in_sizes, int n_in,
                              void* d_out, int out_size)
{
    const int*   s2m_src = (const int*)d_in[0];
    const int*   s2m_dst = (const int*)d_in[1];
    const int*   m2m_src = (const int*)d_in[2];
    const int*   m2m_dst = (const int*)d_in[3];
    const int*   lbl_src = (const int*)d_in[4];
    const int*   lbl_dst = (const int*)d_in[5];
    const float* srna    = (const float*)d_in[6];
    const float* mrna    = (const float*)d_in[7];
    const float* sWl     = (const float*)d_in[8];
    const float* sbl     = (const float*)d_in[9];
    const float* sWr     = (const float*)d_in[10];
    const float* rWl     = (const float*)d_in[11];
    const float* rbl     = (const float*)d_in[12];
    const float* rWr     = (const float*)d_in[13];
    const float* gFW     = (const float*)d_in[14];
    const float* gFb     = (const float*)d_in[15];
    const float* gRW     = (const float*)d_in[16];
    const float* gRb     = (const float*)d_in[17];

    const int Es2m = in_sizes[0];
    const int Em2m = in_sizes[2];
    const int Elbl = in_sizes[4];

    float *xs0, *xs1, *xm0, *xm1, *aggm, *aggs, *macc, *xw, *xw2;
    int *offMd, *offSs, *lstMd, *lstSs;
    __nv_bfloat16 *Amh, *Aml, *Ash, *Asl, *Wth, *Wtl;
    cudaGetSymbolAddress((void**)&xs0, g_xs0);
    cudaGetSymbolAddress((void**)&xs1, g_xs1);
    cudaGetSymbolAddress((void**)&xm0, g_xm0);
    cudaGetSymbolAddress((void**)&xm1, g_xm1);
    cudaGetSymbolAddress((void**)&aggm, g_aggm);
    cudaGetSymbolAddress((void**)&aggs, g_aggs);
    cudaGetSymbolAddress((void**)&macc, g_macc);
    cudaGetSymbolAddress((void**)&xw, g_xw);
    cudaGetSymbolAddress((void**)&xw2, g_xw2);
    cudaGetSymbolAddress((void**)&offMd, g_offMd);
    cudaGetSymbolAddress((void**)&offSs, g_offSs);
    cudaGetSymbolAddress((void**)&lstMd, g_lstMd);
    cudaGetSymbolAddress((void**)&lstSs, g_lstSs);
    cudaGetSymbolAddress((void**)&Amh, g_Amh);
    cudaGetSymbolAddress((void**)&Aml, g_Aml);
    cudaGetSymbolAddress((void**)&Ash, g_Ash);
    cudaGetSymbolAddress((void**)&Asl, g_Asl);
    cudaGetSymbolAddress((void**)&Wth, g_Wth);
    cudaGetSymbolAddress((void**)&Wtl, g_Wtl);

    cudaFuncSetAttribute(gemm_bf16_split,
                         cudaFuncAttributeMaxDynamicSharedMemorySize, GEMM_SMEM);

    const size_t WSZ = (size_t)HID * HID;
    // slots: l*6 + {0:sWl,1:sWr,2:rWl,3:rWr,4:gFW,5:gRW}
    for (int l = 0; l < NLAYERS; l++) {
        const float* Ws[6] = { sWl + l * WSZ, sWr + l * WSZ, rWl + l * WSZ,
                               rWr + l * WSZ, gFW + l * WSZ, gRW + l * WSZ };
        for (int j = 0; j < 6; j++) {
            int slot = l * 6 + j;
            wsplit_kernel<<<(HID * HID + 255) / 256, 256>>>(Ws[j], Wth + slot * WSZ, Wtl + slot * WSZ);
        }
    }

    // ---- CSR build ----
    zero_counts_kernel<<<(NM + 255) / 256, 256>>>();
    hist_s2m_kernel<<<(Es2m + 255) / 256, 256>>>(s2m_src, s2m_dst, Es2m);
    hist_m2m_kernel<<<(Em2m + 255) / 256, 256>>>(m2m_src, m2m_dst, Em2m);
    {
        dim3 g((NM + 1023) / 1024, 4);
        scan_partial_kernel<<<g, 1024>>>();
        scan_fix_kernel<<<g, 1024>>>();
    }
    fill_s2m_kernel<<<(Es2m + 255) / 256, 256>>>(s2m_src, s2m_dst, Es2m);
    fill_m2m_kernel<<<(Em2m + 255) / 256, 256>>>(m2m_src, m2m_dst, Em2m);
    deg_kernel<<<(NM + 255) / 256, 256>>>();

    const float* xsi = srna;
    const float* xmi = mrna;
    const unsigned gm = NMP / 128;   // 782
    const unsigned gs = NSP / 128;   // 157

    for (int l = 0; l < NLAYERS; l++) {
        float* xso = (l == 0) ? xs0 : xs1;
        float* xmo = (l == 0) ? xm0 : xm1;
        int s6 = l * 6;

        // ---- mRNA side ----
        gather_mean_kernel<<<(NM * 32 + 255) / 256, 256>>>(offMd, lstMd, xsi, aggm, NM);
        split_kernel<<<(NM * 32 + 255) / 256, 256>>>(xmi, Amh, Aml, NM * 32);
        gemm_bf16_split<<<gm, 256, GEMM_SMEM>>>(Amh, Aml, Wth + (s6 + 1) * WSZ, Wtl + (s6 + 1) * WSZ,
                                                macc, NM, nullptr, 0);                  // x@sWr
        gemm_bf16_split<<<gm, 256, GEMM_SMEM>>>(Amh, Aml, Wth + (s6 + 4) * WSZ, Wtl + (s6 + 4) * WSZ,
                                                xw, NM, nullptr, 0);                    // x@gFW
        gemm_bf16_split<<<gm, 256, GEMM_SMEM>>>(Amh, Aml, Wth + (s6 + 5) * WSZ, Wtl + (s6 + 5) * WSZ,
                                                xw2, NM, nullptr, 0);                   // x@gRW
        split_kernel<<<(NM * 32 + 255) / 256, 256>>>(aggm, Amh, Aml, NM * 32);
        gemm_bf16_split<<<gm, 256, GEMM_SMEM>>>(Amh, Aml, Wth + (s6 + 0) * WSZ, Wtl + (s6 + 0) * WSZ,
                                                macc, NM, sbl + l * HID, FLAG_ACC);     // agg@sWl
        gcn_fused_kernel<<<(NM * 32 + 255) / 256, 256>>>(gFb + l * HID, gRb + l * HID, xmo);

        // ---- sRNA side (uses OLD x_m) ----
        gather_mean_kernel<<<(NS * 32 + 255) / 256, 256>>>(offSs, lstSs, xmi, aggs, NS);
        split_kernel<<<(NS * 32 + 255) / 256, 256>>>(xsi, Ash, Asl, NS * 32);
        gemm_bf16_split<<<gs, 256, GEMM_SMEM>>>(Ash, Asl, Wth + (s6 + 3) * WSZ, Wtl + (s6 + 3) * WSZ,
                                                xso, NS, nullptr, 0);                   // x@rWr
        split_kernel<<<(NS * 32 + 255) / 256, 256>>>(aggs, Ash, Asl, NS * 32);
        gemm_bf16_split<<<gs, 256, GEMM_SMEM>>>(Ash, Asl, Wth + (s6 + 2) * WSZ, Wtl + (s6 + 2) * WSZ,
                                                xso, NS, rbl + l * HID, FLAG_ACC | FLAG_RELU);
        xsi = xso;
        xmi = xmo;
    }

    {
        long long th = (long long)Elbl * 32;
        classify_kernel<<<(unsigned)((th + 255) / 256), 256>>>(lbl_src, lbl_dst, xsi, xmi, (float*)d_out, Elbl);
    }
}

// round 5
// speedup vs baseline: 2.0731x; 1.0291x over previous
#include <cuda_runtime.h>
#include <cuda_bf16.h>
#include <cstddef>
#include <cstdint>

#define HID 128
#define NS  20000
#define NM  100000
#define NSP 20096
#define NMP 100096
#define ES2M 1000000
#define EM2M 2000000
#define NLAYERS 2

#define FLAG_ACC  1
#define FLAG_RELU 2

#define GEMM_SMEM (2 * 128 * 136 * 2)   // Bh + Bl, bf16, padded pitch 136

// ---------------- scratch (static __device__, no allocation) ----------------
__device__ __align__(16) float g_xs0[NS * HID];
__device__ __align__(16) float g_xs1[NS * HID];
__device__ __align__(16) float g_xm0[NM * HID];
__device__ __align__(16) float g_xm1[NM * HID];
__device__ __align__(16) float g_macc[NM * HID];
__device__ __align__(16) float g_xw [NM * HID];
__device__ __align__(16) float g_xw2[NM * HID];
__device__ float g_dF [NM];
__device__ float g_dR [NM];

// split-bf16 operand buffers (padded rows stay zero from BSS; never written)
__device__ __align__(16) __nv_bfloat16 g_Xmh[NMP * HID];   // x_m split
__device__ __align__(16) __nv_bfloat16 g_Xml[NMP * HID];
__device__ __align__(16) __nv_bfloat16 g_Magh[NMP * HID];  // mean-agg (mRNA dst) split
__device__ __align__(16) __nv_bfloat16 g_Magl[NMP * HID];
__device__ __align__(16) __nv_bfloat16 g_Xsh[NSP * HID];   // x_s split
__device__ __align__(16) __nv_bfloat16 g_Xsl[NSP * HID];
__device__ __align__(16) __nv_bfloat16 g_Sagh[NSP * HID];  // mean-agg (sRNA dst) split
__device__ __align__(16) __nv_bfloat16 g_Sagl[NSP * HID];
__device__ __align__(16) __nv_bfloat16 g_Wth[12 * HID * HID];
__device__ __align__(16) __nv_bfloat16 g_Wtl[12 * HID * HID];

// CSR scratch
__device__ int g_cntMd[NM];
__device__ int g_cntSs[NS];
__device__ int g_cntF [NM];
__device__ int g_cntR [NM];
__device__ int g_offMd[NM + 1];
__device__ int g_offSs[NS + 1];
__device__ int g_offF [NM + 1];
__device__ int g_offR [NM + 1];
__device__ int g_curMd[NM];
__device__ int g_curSs[NS];
__device__ int g_curF [NM];
__device__ int g_curR [NM];
__device__ int g_lstMd[ES2M];
__device__ int g_lstSs[ES2M];
__device__ int g_lstF [EM2M];
__device__ int g_lstR [EM2M];
__device__ int g_bsum[4][128];

// ---------------- helpers ----------------
__device__ __forceinline__ uint32_t pack_hi(float a, float b) {
    __nv_bfloat162 t(__float2bfloat16(a), __float2bfloat16(b));
    return *reinterpret_cast<uint32_t*>(&t);
}
__device__ __forceinline__ void split2(float a, float b, uint32_t& h, uint32_t& l) {
    __nv_bfloat16 ha = __float2bfloat16(a), hb = __float2bfloat16(b);
    __nv_bfloat162 th(ha, hb);
    __nv_bfloat162 tl(__float2bfloat16(a - __bfloat162float(ha)),
                      __float2bfloat16(b - __bfloat162float(hb)));
    h = *reinterpret_cast<uint32_t*>(&th);
    l = *reinterpret_cast<uint32_t*>(&tl);
}

// ---------------- CSR build ----------------
__global__ void zero_counts_kernel() {
    int i = blockIdx.x * blockDim.x + threadIdx.x;
    if (i < NM) { g_cntMd[i] = 0; g_cntF[i] = 0; g_cntR[i] = 0; }
    if (i < NS) { g_cntSs[i] = 0; }
}

__global__ void hist_s2m_kernel(const int* __restrict__ src, const int* __restrict__ dst, int E) {
    int e = blockIdx.x * blockDim.x + threadIdx.x;
    if (e >= E) return;
    atomicAdd(&g_cntMd[dst[e]], 1);
    atomicAdd(&g_cntSs[src[e]], 1);
}

__global__ void hist_m2m_kernel(const int* __restrict__ src, const int* __restrict__ dst, int E) {
    int e = blockIdx.x * blockDim.x + threadIdx.x;
    if (e >= E) return;
    atomicAdd(&g_cntF[dst[e]], 1);
    atomicAdd(&g_cntR[src[e]], 1);
}

__device__ __forceinline__ void sel_arrays(int arr, const int*& cnt, int*& off, int*& cur, int& n) {
    switch (arr) {
        case 0: cnt = g_cntMd; off = g_offMd; cur = g_curMd; n = NM; break;
        case 1: cnt = g_cntSs; off = g_offSs; cur = g_curSs; n = NS; break;
        case 2: cnt = g_cntF;  off = g_offF;  cur = g_curF;  n = NM; break;
        default: cnt = g_cntR; off = g_offR;  cur = g_curR;  n = NM; break;
    }
}

__global__ void __launch_bounds__(1024) scan_partial_kernel() {
    const int* cnt; int* off; int* cur; int n;
    sel_arrays(blockIdx.y, cnt, off, cur, n);
    __shared__ int warpsums[32];
    int tid = threadIdx.x, lane = tid & 31, wid = tid >> 5;
    int i = blockIdx.x * 1024 + tid;
    int v = (i < n) ? cnt[i] : 0;
    int x = v;
#pragma unroll
    for (int o = 1; o < 32; o <<= 1) {
        int t = __shfl_up_sync(0xffffffffu, x, o);
        if (lane >= o) x += t;
    }
    if (lane == 31) warpsums[wid] = x;
    __syncthreads();
    if (wid == 0) {
        int w = warpsums[lane];
#pragma unroll
        for (int o = 1; o < 32; o <<= 1) {
            int t = __shfl_up_sync(0xffffffffu, w, o);
            if (lane >= o) w += t;
        }
        warpsums[lane] = w;
    }
    __syncthreads();
    int excl = x - v + (wid ? warpsums[wid - 1] : 0);
    if (i < n) { off[i] = excl; cur[i] = excl; }
    if (tid == 1023) g_bsum[blockIdx.y][blockIdx.x] = excl + v;
}

__global__ void __launch_bounds__(1024) scan_fix_kernel() {
    const int* cnt; int* off; int* cur; int n;
    sel_arrays(blockIdx.y, cnt, off, cur, n);
    __shared__ int sbase;
    int tid = threadIdx.x;
    if (tid < 32) {
        int s = 0;
        for (int j = tid; j < (int)blockIdx.x; j += 32) s += g_bsum[blockIdx.y][j];
#pragma unroll
        for (int o = 16; o > 0; o >>= 1) s += __shfl_xor_sync(0xffffffffu, s, o);
        if (tid == 0) sbase = s;
    }
    __syncthreads();
    int b = sbase;
    int i = blockIdx.x * 1024 + tid;
    if (i < n) { off[i] += b; cur[i] += b; }
    if (blockIdx.x == gridDim.x - 1 && tid == 0)
        off[n] = b + g_bsum[blockIdx.y][blockIdx.x];
}

__global__ void fill_s2m_kernel(const int* __restrict__ src, const int* __restrict__ dst, int E) {
    int e = blockIdx.x * blockDim.x + threadIdx.x;
    if (e >= E) return;
    int s = src[e], d = dst[e];
    g_lstMd[atomicAdd(&g_curMd[d], 1)] = s;
    g_lstSs[atomicAdd(&g_curSs[s], 1)] = d;
}

__global__ void fill_m2m_kernel(const int* __restrict__ src, const int* __restrict__ dst, int E) {
    int e = blockIdx.x * blockDim.x + threadIdx.x;
    if (e >= E) return;
    int s = src[e], d = dst[e];
    g_lstF[atomicAdd(&g_curF[d], 1)] = s;
    g_lstR[atomicAdd(&g_curR[s], 1)] = d;
}

__global__ void deg_kernel() {
    int i = blockIdx.x * blockDim.x + threadIdx.x;
    if (i < NM) {
        g_dF[i] = rsqrtf((float)g_cntF[i] + 1.0f);
        g_dR[i] = rsqrtf((float)g_cntR[i] + 1.0f);
    }
}

// ---------------- initial split conversion (fp32 -> hi/lo bf16) ----------------
__global__ void __launch_bounds__(256) split_kernel(
    const float* __restrict__ X,
    __nv_bfloat16* __restrict__ hi, __nv_bfloat16* __restrict__ lo, int n4)
{
    int i = blockIdx.x * blockDim.x + threadIdx.x;
    if (i >= n4) return;
    float4 v = reinterpret_cast<const float4*>(X)[i];
    uint2 uh, ul;
    split2(v.x, v.y, uh.x, ul.x);
    split2(v.z, v.w, uh.y, ul.y);
    reinterpret_cast<uint2*>(hi)[i] = uh;
    reinterpret_cast<uint2*>(lo)[i] = ul;
}

// weight: W[k][n] (row-major KxN) -> Bt[n][k] split
__global__ void wsplit_kernel(const float* __restrict__ W,
                              __nv_bfloat16* __restrict__ oh,
                              __nv_bfloat16* __restrict__ ol)
{
    int i = blockIdx.x * blockDim.x + threadIdx.x;
    if (i >= HID * HID) return;
    int k = i >> 7, n = i & 127;
    float x = W[i];
    __nv_bfloat16 h = __float2bfloat16(x);
    oh[n * 128 + k] = h;
    ol[n * 128 + k] = __float2bfloat16(x - __bfloat162float(h));
}

// ---------------- tensor-core GEMM (split bf16, 3-product fp32 emulation) ----------------
__device__ __forceinline__ void mma16816(float* c,
    uint32_t a0, uint32_t a1, uint32_t a2, uint32_t a3,
    uint32_t b0, uint32_t b1)
{
    asm volatile("mma.sync.aligned.m16n8k16.row.col.f32.bf16.bf16.f32 "
        "{%0,%1,%2,%3}, {%4,%5,%6,%7}, {%8,%9}, {%0,%1,%2,%3};"
        : "+f"(c[0]), "+f"(c[1]), "+f"(c[2]), "+f"(c[3])
        : "r"(a0), "r"(a1), "r"(a2), "r"(a3), "r"(b0), "r"(b1));
}

// D[M,128] (+)= A[M,128] @ W[128,128] (+bias)(relu). Optional split bf16 copy of D.
__global__ void __launch_bounds__(256) gemm_bf16_split(
    const __nv_bfloat16* __restrict__ Ahi, const __nv_bfloat16* __restrict__ Alo,
    const __nv_bfloat16* __restrict__ Bthi, const __nv_bfloat16* __restrict__ Btlo,
    float* __restrict__ D, int M, const float* __restrict__ bias, int flags,
    __nv_bfloat16* __restrict__ Oh, __nv_bfloat16* __restrict__ Ol)
{
    extern __shared__ __nv_bfloat16 sh[];
    __nv_bfloat16* Bh = sh;                 // [128][136]
    __nv_bfloat16* Bl = sh + 128 * 136;
    int tid = threadIdx.x;
    for (int i = tid; i < 128 * 64; i += 256) {
        int r = i >> 6, c = i & 63;
        reinterpret_cast<uint32_t*>(Bh + r * 136)[c] = reinterpret_cast<const uint32_t*>(Bthi)[i];
        reinterpret_cast<uint32_t*>(Bl + r * 136)[c] = reinterpret_cast<const uint32_t*>(Btlo)[i];
    }
    __syncthreads();

    int warp = tid >> 5, lane = tid & 31;
    int g = lane >> 2, t4 = lane & 3;
    int m0 = blockIdx.x * 128 + warp * 16;
    const uint32_t* ah = reinterpret_cast<const uint32_t*>(Ahi) + (size_t)m0 * 64;
    const uint32_t* al = reinterpret_cast<const uint32_t*>(Alo) + (size_t)m0 * 64;

    float acc[16][4];
#pragma unroll
    for (int nf = 0; nf < 16; nf++)
#pragma unroll
        for (int j = 0; j < 4; j++) acc[nf][j] = 0.f;

#pragma unroll 2
    for (int k0 = 0; k0 < 8; k0++) {
        int kb = k0 * 8;
        uint32_t a0h = ah[g * 64 + kb + t4];
        uint32_t a1h = ah[(g + 8) * 64 + kb + t4];
        uint32_t a2h = ah[g * 64 + kb + t4 + 4];
        uint32_t a3h = ah[(g + 8) * 64 + kb + t4 + 4];
        uint32_t a0l = al[g * 64 + kb + t4];
        uint32_t a1l = al[(g + 8) * 64 + kb + t4];
        uint32_t a2l = al[g * 64 + kb + t4 + 4];
        uint32_t a3l = al[(g + 8) * 64 + kb + t4 + 4];
#pragma unroll
        for (int nf = 0; nf < 16; nf++) {
            int n = nf * 8 + g;
            const uint32_t* bh = reinterpret_cast<const uint32_t*>(Bh + n * 136);
            const uint32_t* bl = reinterpret_cast<const uint32_t*>(Bl + n * 136);
            uint32_t b0h = bh[kb + t4], b1h = bh[kb + t4 + 4];
            uint32_t b0l = bl[kb + t4], b1l = bl[kb + t4 + 4];
            mma16816(acc[nf], a0h, a1h, a2h, a3h, b0h, b1h);
            mma16816(acc[nf], a0h, a1h, a2h, a3h, b0l, b1l);
            mma16816(acc[nf], a0l, a1l, a2l, a3l, b0h, b1h);
        }
    }

    int r0 = m0 + g, r1 = m0 + g + 8;
#pragma unroll
    for (int nf = 0; nf < 16; nf++) {
        int c = nf * 8 + t4 * 2;
        float bx = 0.f, by = 0.f;
        if (bias) { float2 bv = *reinterpret_cast<const float2*>(&bias[c]); bx = bv.x; by = bv.y; }
        if (r0 < M) {
            float2* p = reinterpret_cast<float2*>(&D[(size_t)r0 * 128 + c]);
            float2 o = make_float2(acc[nf][0] + bx, acc[nf][1] + by);
            if (flags & FLAG_ACC) { float2 d = *p; o.x += d.x; o.y += d.y; }
            if (flags & FLAG_RELU) { o.x = fmaxf(o.x, 0.f); o.y = fmaxf(o.y, 0.f); }
            *p = o;
            if (Oh) {
                uint32_t h, l;
                split2(o.x, o.y, h, l);
                *reinterpret_cast<uint32_t*>(&Oh[(size_t)r0 * 128 + c]) = h;
                *reinterpret_cast<uint32_t*>(&Ol[(size_t)r0 * 128 + c]) = l;
            }
        }
        if (r1 < M) {
            float2* p = reinterpret_cast<float2*>(&D[(size_t)r1 * 128 + c]);
            float2 o = make_float2(acc[nf][2] + bx, acc[nf][3] + by);
            if (flags & FLAG_ACC) { float2 d = *p; o.x += d.x; o.y += d.y; }
            if (flags & FLAG_RELU) { o.x = fmaxf(o.x, 0.f); o.y = fmaxf(o.y, 0.f); }
            *p = o;
            if (Oh) {
                uint32_t h, l;
                split2(o.x, o.y, h, l);
                *reinterpret_cast<uint32_t*>(&Oh[(size_t)r1 * 128 + c]) = h;
                *reinterpret_cast<uint32_t*>(&Ol[(size_t)r1 * 128 + c]) = l;
            }
        }
    }
}

// ---------------- gathers (warp per dst row, no atomics) ----------------
// mean over CSR neighbors, written directly as hi/lo bf16 split
__global__ void __launch_bounds__(256) gather_mean_split_kernel(
    const int* __restrict__ off, const int* __restrict__ lst,
    const float* __restrict__ X,
    __nv_bfloat16* __restrict__ Oh, __nv_bfloat16* __restrict__ Ol, int n)
{
    int w = (blockIdx.x * blockDim.x + threadIdx.x) >> 5;
    if (w >= n) return;
    int lane = threadIdx.x & 31;
    int s = off[w], e = off[w + 1];
    float4 a0 = make_float4(0.f, 0.f, 0.f, 0.f);
    float4 a1 = make_float4(0.f, 0.f, 0.f, 0.f);
    int i = s;
    for (; i + 1 < e; i += 2) {
        int p0 = lst[i], p1 = lst[i + 1];
        float4 v0 = *reinterpret_cast<const float4*>(&X[(size_t)p0 * HID + lane * 4]);
        float4 v1 = *reinterpret_cast<const float4*>(&X[(size_t)p1 * HID + lane * 4]);
        a0.x += v0.x; a0.y += v0.y; a0.z += v0.z; a0.w += v0.w;
        a1.x += v1.x; a1.y += v1.y; a1.z += v1.z; a1.w += v1.w;
    }
    if (i < e) {
        int p0 = lst[i];
        float4 v0 = *reinterpret_cast<const float4*>(&X[(size_t)p0 * HID + lane * 4]);
        a0.x += v0.x; a0.y += v0.y; a0.z += v0.z; a0.w += v0.w;
    }
    float inv = 1.0f / fmaxf((float)(e - s), 1.0f);
    float ox = (a0.x + a1.x) * inv, oy = (a0.y + a1.y) * inv;
    float oz = (a0.z + a1.z) * inv, ow = (a0.w + a1.w) * inv;
    uint2 uh, ul;
    split2(ox, oy, uh.x, ul.x);
    split2(oz, ow, uh.y, ul.y);
    reinterpret_cast<uint2*>(&Oh[(size_t)w * HID])[lane] = uh;
    reinterpret_cast<uint2*>(&Ol[(size_t)w * HID])[lane] = ul;
}

// fused GCN fwd+rev gather + self-loops + biases + relu -> out fp32 (+ split copy)
__global__ void __launch_bounds__(256) gcn_fused_kernel(
    const float* __restrict__ bF, const float* __restrict__ bR,
    float* __restrict__ out,
    __nv_bfloat16* __restrict__ Oh, __nv_bfloat16* __restrict__ Ol)
{
    int w = (blockIdx.x * blockDim.x + threadIdx.x) >> 5;
    if (w >= NM) return;
    int lane = threadIdx.x & 31;
    size_t ro = (size_t)w * HID + lane * 4;

    float4 aF = make_float4(0.f, 0.f, 0.f, 0.f);
    {
        int s = g_offF[w], e = g_offF[w + 1];
        float4 t1 = make_float4(0.f, 0.f, 0.f, 0.f);
        int i = s;
        for (; i + 1 < e; i += 2) {
            int p0 = g_lstF[i], p1 = g_lstF[i + 1];
            float w0 = g_dF[p0], w1 = g_dF[p1];
            float4 v0 = *reinterpret_cast<const float4*>(&g_xw[(size_t)p0 * HID + lane * 4]);
            float4 v1 = *reinterpret_cast<const float4*>(&g_xw[(size_t)p1 * HID + lane * 4]);
            aF.x += w0 * v0.x; aF.y += w0 * v0.y; aF.z += w0 * v0.z; aF.w += w0 * v0.w;
            t1.x += w1 * v1.x; t1.y += w1 * v1.y; t1.z += w1 * v1.z; t1.w += w1 * v1.w;
        }
        if (i < e) {
            int p0 = g_lstF[i];
            float w0 = g_dF[p0];
            float4 v0 = *reinterpret_cast<const float4*>(&g_xw[(size_t)p0 * HID + lane * 4]);
            aF.x += w0 * v0.x; aF.y += w0 * v0.y; aF.z += w0 * v0.z; aF.w += w0 * v0.w;
        }
        aF.x += t1.x; aF.y += t1.y; aF.z += t1.z; aF.w += t1.w;
    }
    float4 aR = make_float4(0.f, 0.f, 0.f, 0.f);
    {
        int s = g_offR[w], e = g_offR[w + 1];
        float4 t1 = make_float4(0.f, 0.f, 0.f, 0.f);
        int i = s;
        for (; i + 1 < e; i += 2) {
            int p0 = g_lstR[i], p1 = g_lstR[i + 1];
            float w0 = g_dR[p0], w1 = g_dR[p1];
            float4 v0 = *reinterpret_cast<const float4*>(&g_xw2[(size_t)p0 * HID + lane * 4]);
            float4 v1 = *reinterpret_cast<const float4*>(&g_xw2[(size_t)p1 * HID + lane * 4]);
            aR.x += w0 * v0.x; aR.y += w0 * v0.y; aR.z += w0 * v0.z; aR.w += w0 * v0.w;
            t1.x += w1 * v1.x; t1.y += w1 * v1.y; t1.z += w1 * v1.z; t1.w += w1 * v1.w;
        }
        if (i < e) {
            int p0 = g_lstR[i];
            float w0 = g_dR[p0];
            float4 v0 = *reinterpret_cast<const float4*>(&g_xw2[(size_t)p0 * HID + lane * 4]);
            aR.x += w0 * v0.x; aR.y += w0 * v0.y; aR.z += w0 * v0.z; aR.w += w0 * v0.w;
        }
        aR.x += t1.x; aR.y += t1.y; aR.z += t1.z; aR.w += t1.w;
    }

    float f = g_dF[w], r = g_dR[w];
    float f2 = f * f, r2 = r * r;
    float4 m  = *reinterpret_cast<const float4*>(&g_macc[ro]);
    float4 xv = *reinterpret_cast<const float4*>(&g_xw[ro]);
    float4 x2 = *reinterpret_cast<const float4*>(&g_xw2[ro]);
    float4 bf = reinterpret_cast<const float4*>(bF)[lane];
    float4 br = reinterpret_cast<const float4*>(bR)[lane];
    float4 o;
    o.x = fmaxf(m.x + f * aF.x + f2 * xv.x + bf.x + r * aR.x + r2 * x2.x + br.x, 0.f);
    o.y = fmaxf(m.y + f * aF.y + f2 * xv.y + bf.y + r * aR.y + r2 * x2.y + br.y, 0.f);
    o.z = fmaxf(m.z + f * aF.z + f2 * xv.z + bf.z + r * aR.z + r2 * x2.z + br.z, 0.f);
    o.w = fmaxf(m.w + f * aF.w + f2 * xv.w + bf.w + r * aR.w + r2 * x2.w + br.w, 0.f);
    *reinterpret_cast<float4*>(&out[ro]) = o;
    if (Oh) {
        uint2 uh, ul;
        split2(o.x, o.y, uh.x, ul.x);
        split2(o.z, o.w, uh.y, ul.y);
        reinterpret_cast<uint2*>(&Oh[(size_t)w * HID])[lane] = uh;
        reinterpret_cast<uint2*>(&Ol[(size_t)w * HID])[lane] = ul;
    }
}

// ---------------- classifier ----------------
__global__ void __launch_bounds__(256) classify_kernel(
    const int* __restrict__ ls, const int* __restrict__ ld,
    const float* __restrict__ XS, const float* __restrict__ XM,
    float* __restrict__ out, int E)
{
    long long t = (long long)blockIdx.x * blockDim.x + threadIdx.x;
    int e = (int)(t >> 5);
    if (e >= E) return;
    int lane = (int)(t & 31);
    int s = ls[e], d = ld[e];
    float4 a = *reinterpret_cast<const float4*>(&XS[(size_t)s * HID + lane * 4]);
    float4 b = *reinterpret_cast<const float4*>(&XM[(size_t)d * HID + lane * 4]);
    float p = a.x * b.x + a.y * b.y + a.z * b.z + a.w * b.w;
#pragma unroll
    for (int o = 16; o > 0; o >>= 1) p += __shfl_xor_sync(0xffffffffu, p, o);
    if (lane == 0) out[e] = p;
}

// ---------------- host ----------------
extern "C" void kernel_launch(void* const* d_in, const int* in_sizes, int n_in,
                              void* d_out, int out_size)
{
    const int*   s2m_src = (const int*)d_in[0];
    const int*   s2m_dst = (const int*)d_in[1];
    const int*   m2m_src = (const int*)d_in[2];
    const int*   m2m_dst = (const int*)d_in[3];
    const int*   lbl_src = (const int*)d_in[4];
    const int*   lbl_dst = (const int*)d_in[5];
    const float* srna    = (const float*)d_in[6];
    const float* mrna    = (const float*)d_in[7];
    const float* sWl     = (const float*)d_in[8];
    const float* sbl     = (const float*)d_in[9];
    const float* sWr     = (const float*)d_in[10];
    const float* rWl     = (const float*)d_in[11];
    const float* rbl     = (const float*)d_in[12];
    const float* rWr     = (const float*)d_in[13];
    const float* gFW     = (const float*)d_in[14];
    const float* gFb     = (const float*)d_in[15];
    const float* gRW     = (const float*)d_in[16];
    const float* gRb     = (const float*)d_in[17];

    const int Es2m = in_sizes[0];
    const int Em2m = in_sizes[2];
    const int Elbl = in_sizes[4];

    float *xs0, *xs1, *xm0, *xm1, *macc, *xw, *xw2;
    int *offMd, *offSs, *lstMd, *lstSs;
    __nv_bfloat16 *Xmh, *Xml, *Magh, *Magl, *Xsh, *Xsl, *Sagh, *Sagl, *Wth, *Wtl;
    cudaGetSymbolAddress((void**)&xs0, g_xs0);
    cudaGetSymbolAddress((void**)&xs1, g_xs1);
    cudaGetSymbolAddress((void**)&xm0, g_xm0);
    cudaGetSymbolAddress((void**)&xm1, g_xm1);
    cudaGetSymbolAddress((void**)&macc, g_macc);
    cudaGetSymbolAddress((void**)&xw, g_xw);
    cudaGetSymbolAddress((void**)&xw2, g_xw2);
    cudaGetSymbolAddress((void**)&offMd, g_offMd);
    cudaGetSymbolAddress((void**)&offSs, g_offSs);
    cudaGetSymbolAddress((void**)&lstMd, g_lstMd);
    cudaGetSymbolAddress((void**)&lstSs, g_lstSs);
    cudaGetSymbolAddress((void**)&Xmh, g_Xmh);
    cudaGetSymbolAddress((void**)&Xml, g_Xml);
    cudaGetSymbolAddress((void**)&Magh, g_Magh);
    cudaGetSymbolAddress((void**)&Magl, g_Magl);
    cudaGetSymbolAddress((void**)&Xsh, g_Xsh);
    cudaGetSymbolAddress((void**)&Xsl, g_Xsl);
    cudaGetSymbolAddress((void**)&Sagh, g_Sagh);
    cudaGetSymbolAddress((void**)&Sagl, g_Sagl);
    cudaGetSymbolAddress((void**)&Wth, g_Wth);
    cudaGetSymbolAddress((void**)&Wtl, g_Wtl);

    cudaFuncSetAttribute(gemm_bf16_split,
                         cudaFuncAttributeMaxDynamicSharedMemorySize, GEMM_SMEM);

    // one-time resources (host-side only; no device allocation)
    static cudaStream_t s2 = nullptr;
    static cudaEvent_t ev[6];
    if (!s2) {
        cudaStreamCreateWithFlags(&s2, cudaStreamNonBlocking);
        for (int i = 0; i < 6; i++) cudaEventCreateWithFlags(&ev[i], cudaEventDisableTiming);
    }

    const size_t WSZ = (size_t)HID * HID;

    // ---- fork: side stream does initial splits while main does weight split + CSR ----
    cudaEventRecord(ev[0], 0);
    cudaStreamWaitEvent(s2, ev[0], 0);
    split_kernel<<<(NM * 32 + 255) / 256, 256, 0, s2>>>(mrna, Xmh, Xml, NM * 32);
    split_kernel<<<(NS * 32 + 255) / 256, 256, 0, s2>>>(srna, Xsh, Xsl, NS * 32);

    for (int l = 0; l < NLAYERS; l++) {
        const float* Ws[6] = { sWl + l * WSZ, sWr + l * WSZ, rWl + l * WSZ,
                               rWr + l * WSZ, gFW + l * WSZ, gRW + l * WSZ };
        for (int j = 0; j < 6; j++) {
            int slot = l * 6 + j;
            wsplit_kernel<<<(HID * HID + 255) / 256, 256>>>(Ws[j], Wth + slot * WSZ, Wtl + slot * WSZ);
        }
    }
    zero_counts_kernel<<<(NM + 255) / 256, 256>>>();
    hist_s2m_kernel<<<(Es2m + 255) / 256, 256>>>(s2m_src, s2m_dst, Es2m);
    hist_m2m_kernel<<<(Em2m + 255) / 256, 256>>>(m2m_src, m2m_dst, Em2m);
    {
        dim3 g((NM + 1023) / 1024, 4);
        scan_partial_kernel<<<g, 1024>>>();
        scan_fix_kernel<<<g, 1024>>>();
    }
    fill_s2m_kernel<<<(Es2m + 255) / 256, 256>>>(s2m_src, s2m_dst, Es2m);
    fill_m2m_kernel<<<(Em2m + 255) / 256, 256>>>(m2m_src, m2m_dst, Em2m);
    deg_kernel<<<(NM + 255) / 256, 256>>>();
    // join initial splits back into main
    cudaEventRecord(ev[1], s2);
    cudaStreamWaitEvent(0, ev[1], 0);

    const float* xsi = srna;
    const float* xmi = mrna;
    const unsigned gm = NMP / 128;
    const unsigned gs = NSP / 128;

    for (int l = 0; l < NLAYERS; l++) {
        float* xso = (l == 0) ? xs0 : xs1;
        float* xmo = (l == 0) ? xm0 : xm1;
        int s6 = l * 6;

        // fork: side stream runs the two mean gathers (L2-bound)
        cudaEventRecord(ev[2], 0);
        cudaStreamWaitEvent(s2, ev[2], 0);
        gather_mean_split_kernel<<<(NM * 32 + 255) / 256, 256, 0, s2>>>(offMd, lstMd, xsi, Magh, Magl, NM);
        gather_mean_split_kernel<<<(NS * 32 + 255) / 256, 256, 0, s2>>>(offSs, lstSs, xmi, Sagh, Sagl, NS);
        cudaEventRecord(ev[3], s2);

        // main: 3 GEMMs on x_m (tensor-bound), independent of gathers
        gemm_bf16_split<<<gm, 256, GEMM_SMEM>>>(Xmh, Xml, Wth + (s6 + 1) * WSZ, Wtl + (s6 + 1) * WSZ,
                                                macc, NM, nullptr, 0, nullptr, nullptr);       // x@sWr
        gemm_bf16_split<<<gm, 256, GEMM_SMEM>>>(Xmh, Xml, Wth + (s6 + 4) * WSZ, Wtl + (s6 + 4) * WSZ,
                                                xw, NM, nullptr, 0, nullptr, nullptr);         // x@gFW
        gemm_bf16_split<<<gm, 256, GEMM_SMEM>>>(Xmh, Xml, Wth + (s6 + 5) * WSZ, Wtl + (s6 + 5) * WSZ,
                                                xw2, NM, nullptr, 0, nullptr, nullptr);        // x@gRW
        cudaStreamWaitEvent(0, ev[3], 0);
        gemm_bf16_split<<<gm, 256, GEMM_SMEM>>>(Magh, Magl, Wth + (s6 + 0) * WSZ, Wtl + (s6 + 0) * WSZ,
                                                macc, NM, sbl + l * HID, FLAG_ACC, nullptr, nullptr);
        cudaEventRecord(ev[4], 0);

        // side: gcn_fused (memory-bound) produces xmo + its split for next layer
        cudaStreamWaitEvent(s2, ev[4], 0);
        gcn_fused_kernel<<<(NM * 32 + 255) / 256, 256, 0, s2>>>(gFb + l * HID, gRb + l * HID, xmo, Xmh, Xml);
        cudaEventRecord(ev[5], s2);

        // main: sRNA GEMMs (tensor-bound) overlap gcn_fused
        gemm_bf16_split<<<gs, 256, GEMM_SMEM>>>(Xsh, Xsl, Wth + (s6 + 3) * WSZ, Wtl + (s6 + 3) * WSZ,
                                                xso, NS, nullptr, 0, nullptr, nullptr);        // x@rWr
        gemm_bf16_split<<<gs, 256, GEMM_SMEM>>>(Sagh, Sagl, Wth + (s6 + 2) * WSZ, Wtl + (s6 + 2) * WSZ,
                                                xso, NS, rbl + l * HID, FLAG_ACC | FLAG_RELU, Xsh, Xsl);
        cudaStreamWaitEvent(0, ev[5], 0);   // join: xmo + Xm split ready

        xsi = xso;
        xmi = xmo;
    }

    {
        long long th = (long long)Elbl * 32;
        classify_kernel<<<(unsigned)((th + 255) / 256), 256>>>(lbl_src, lbl_dst, xsi, xmi, (float*)d_out, Elbl);
    }
}

// round 6
// speedup vs baseline: 2.3648x; 1.1408x over previous
#include <cuda_runtime.h>
#include <cuda_bf16.h>
#include <cstddef>
#include <cstdint>

#define HID 128
#define NS  20000
#define NM  100000
#define NSP 20096
#define NMP 100096
#define ES2M 1000000
#define EM2M 2000000
#define NLAYERS 2

#define DUAL_SMEM (4 * 128 * 68 * 4)   // 4 B-tiles as u32 [128][68]

// ---------------- scratch (static __device__, no allocation) ----------------
__device__ __align__(16) float g_xs0[NS * HID];
__device__ __align__(16) float g_xs1[NS * HID];
__device__ __align__(16) float g_xm0[NM * HID];
__device__ __align__(16) float g_xm1[NM * HID];
__device__ __align__(16) float g_macc[NM * HID];
__device__ float g_dF [NM];
__device__ float g_dR [NM];

// split-bf16 operand buffers (padded rows stay zero from BSS)
__device__ __align__(16) __nv_bfloat16 g_Xmh[NMP * HID];
__device__ __align__(16) __nv_bfloat16 g_Xml[NMP * HID];
__device__ __align__(16) __nv_bfloat16 g_Magh[NMP * HID];
__device__ __align__(16) __nv_bfloat16 g_Magl[NMP * HID];
__device__ __align__(16) __nv_bfloat16 g_GFh[NMP * HID];
__device__ __align__(16) __nv_bfloat16 g_GFl[NMP * HID];
__device__ __align__(16) __nv_bfloat16 g_GRh[NMP * HID];
__device__ __align__(16) __nv_bfloat16 g_GRl[NMP * HID];
__device__ __align__(16) __nv_bfloat16 g_Xsh[NSP * HID];
__device__ __align__(16) __nv_bfloat16 g_Xsl[NSP * HID];
__device__ __align__(16) __nv_bfloat16 g_Sagh[NSP * HID];
__device__ __align__(16) __nv_bfloat16 g_Sagl[NSP * HID];
__device__ __align__(16) __nv_bfloat16 g_Wth[12 * HID * HID];
__device__ __align__(16) __nv_bfloat16 g_Wtl[12 * HID * HID];

// CSR scratch
__device__ int g_cntMd[NM];
__device__ int g_cntSs[NS];
__device__ int g_cntF [NM];
__device__ int g_cntR [NM];
__device__ int g_offMd[NM + 1];
__device__ int g_offSs[NS + 1];
__device__ int g_offF [NM + 1];
__device__ int g_offR [NM + 1];
__device__ int g_curMd[NM];
__device__ int g_curSs[NS];
__device__ int g_curF [NM];
__device__ int g_curR [NM];
__device__ int g_lstMd[ES2M];
__device__ int g_lstSs[ES2M];
__device__ int g_lstF [EM2M];
__device__ int g_lstR [EM2M];
__device__ int g_bsum[4][128];

// ---------------- helpers ----------------
__device__ __forceinline__ void split2(float a, float b, uint32_t& h, uint32_t& l) {
    __nv_bfloat16 ha = __float2bfloat16(a), hb = __float2bfloat16(b);
    __nv_bfloat162 th(ha, hb);
    __nv_bfloat162 tl(__float2bfloat16(a - __bfloat162float(ha)),
                      __float2bfloat16(b - __bfloat162float(hb)));
    h = *reinterpret_cast<uint32_t*>(&th);
    l = *reinterpret_cast<uint32_t*>(&tl);
}

// ---------------- CSR build ----------------
__global__ void zero_counts_kernel() {
    int i = blockIdx.x * blockDim.x + threadIdx.x;
    if (i < NM) { g_cntMd[i] = 0; g_cntF[i] = 0; g_cntR[i] = 0; }
    if (i < NS) { g_cntSs[i] = 0; }
}

__global__ void hist_s2m_kernel(const int* __restrict__ src, const int* __restrict__ dst, int E) {
    int e = blockIdx.x * blockDim.x + threadIdx.x;
    if (e >= E) return;
    atomicAdd(&g_cntMd[dst[e]], 1);
    atomicAdd(&g_cntSs[src[e]], 1);
}

__global__ void hist_m2m_kernel(const int* __restrict__ src, const int* __restrict__ dst, int E) {
    int e = blockIdx.x * blockDim.x + threadIdx.x;
    if (e >= E) return;
    atomicAdd(&g_cntF[dst[e]], 1);
    atomicAdd(&g_cntR[src[e]], 1);
}

__device__ __forceinline__ void sel_arrays(int arr, const int*& cnt, int*& off, int*& cur, int& n) {
    switch (arr) {
        case 0: cnt = g_cntMd; off = g_offMd; cur = g_curMd; n = NM; break;
        case 1: cnt = g_cntSs; off = g_offSs; cur = g_curSs; n = NS; break;
        case 2: cnt = g_cntF;  off = g_offF;  cur = g_curF;  n = NM; break;
        default: cnt = g_cntR; off = g_offR;  cur = g_curR;  n = NM; break;
    }
}

__global__ void __launch_bounds__(1024) scan_partial_kernel() {
    const int* cnt; int* off; int* cur; int n;
    sel_arrays(blockIdx.y, cnt, off, cur, n);
    __shared__ int warpsums[32];
    int tid = threadIdx.x, lane = tid & 31, wid = tid >> 5;
    int i = blockIdx.x * 1024 + tid;
    int v = (i < n) ? cnt[i] : 0;
    int x = v;
#pragma unroll
    for (int o = 1; o < 32; o <<= 1) {
        int t = __shfl_up_sync(0xffffffffu, x, o);
        if (lane >= o) x += t;
    }
    if (lane == 31) warpsums[wid] = x;
    __syncthreads();
    if (wid == 0) {
        int w = warpsums[lane];
#pragma unroll
        for (int o = 1; o < 32; o <<= 1) {
            int t = __shfl_up_sync(0xffffffffu, w, o);
            if (lane >= o) w += t;
        }
        warpsums[lane] = w;
    }
    __syncthreads();
    int excl = x - v + (wid ? warpsums[wid - 1] : 0);
    if (i < n) { off[i] = excl; cur[i] = excl; }
    if (tid == 1023) g_bsum[blockIdx.y][blockIdx.x] = excl + v;
}

__global__ void __launch_bounds__(1024) scan_fix_kernel() {
    const int* cnt; int* off; int* cur; int n;
    sel_arrays(blockIdx.y, cnt, off, cur, n);
    __shared__ int sbase;
    int tid = threadIdx.x;
    if (tid < 32) {
        int s = 0;
        for (int j = tid; j < (int)blockIdx.x; j += 32) s += g_bsum[blockIdx.y][j];
#pragma unroll
        for (int o = 16; o > 0; o >>= 1) s += __shfl_xor_sync(0xffffffffu, s, o);
        if (tid == 0) sbase = s;
    }
    __syncthreads();
    int b = sbase;
    int i = blockIdx.x * 1024 + tid;
    if (i < n) { off[i] += b; cur[i] += b; }
    if (blockIdx.x == gridDim.x - 1 && tid == 0)
        off[n] = b + g_bsum[blockIdx.y][blockIdx.x];
}

__global__ void fill_s2m_kernel(const int* __restrict__ src, const int* __restrict__ dst, int E) {
    int e = blockIdx.x * blockDim.x + threadIdx.x;
    if (e >= E) return;
    int s = src[e], d = dst[e];
    g_lstMd[atomicAdd(&g_curMd[d], 1)] = s;
    g_lstSs[atomicAdd(&g_curSs[s], 1)] = d;
}

__global__ void fill_m2m_kernel(const int* __restrict__ src, const int* __restrict__ dst, int E) {
    int e = blockIdx.x * blockDim.x + threadIdx.x;
    if (e >= E) return;
    int s = src[e], d = dst[e];
    g_lstF[atomicAdd(&g_curF[d], 1)] = s;
    g_lstR[atomicAdd(&g_curR[s], 1)] = d;
}

__global__ void deg_kernel() {
    int i = blockIdx.x * blockDim.x + threadIdx.x;
    if (i < NM) {
        g_dF[i] = rsqrtf((float)g_cntF[i] + 1.0f);
        g_dR[i] = rsqrtf((float)g_cntR[i] + 1.0f);
    }
}

// ---------------- initial split conversion ----------------
__global__ void __launch_bounds__(256) split_kernel(
    const float* __restrict__ X,
    __nv_bfloat16* __restrict__ hi, __nv_bfloat16* __restrict__ lo, int n4)
{
    int i = blockIdx.x * blockDim.x + threadIdx.x;
    if (i >= n4) return;
    float4 v = reinterpret_cast<const float4*>(X)[i];
    uint2 uh, ul;
    split2(v.x, v.y, uh.x, ul.x);
    split2(v.z, v.w, uh.y, ul.y);
    reinterpret_cast<uint2*>(hi)[i] = uh;
    reinterpret_cast<uint2*>(lo)[i] = ul;
}

__global__ void wsplit_kernel(const float* __restrict__ W,
                              __nv_bfloat16* __restrict__ oh,
                              __nv_bfloat16* __restrict__ ol)
{
    int i = blockIdx.x * blockDim.x + threadIdx.x;
    if (i >= HID * HID) return;
    int k = i >> 7, n = i & 127;
    float x = W[i];
    __nv_bfloat16 h = __float2bfloat16(x);
    oh[n * 128 + k] = h;
    ol[n * 128 + k] = __float2bfloat16(x - __bfloat162float(h));
}

// ---------------- dual tensor-core GEMM ----------------
__device__ __forceinline__ void mma16816(float* c,
    uint32_t a0, uint32_t a1, uint32_t a2, uint32_t a3,
    uint32_t b0, uint32_t b1)
{
    asm volatile("mma.sync.aligned.m16n8k16.row.col.f32.bf16.bf16.f32 "
        "{%0,%1,%2,%3}, {%4,%5,%6,%7}, {%8,%9}, {%0,%1,%2,%3};"
        : "+f"(c[0]), "+f"(c[1]), "+f"(c[2]), "+f"(c[3])
        : "r"(a0), "r"(a1), "r"(a2), "r"(a3), "r"(b0), "r"(b1));
}

// D = A1@W1 + A2@W2 (+bias1)(+bias2)(+ACCsrc)(relu) -> Dout fp32 (+ split Oh/Ol)
__global__ void __launch_bounds__(256) gemm_dual(
    const __nv_bfloat16* __restrict__ A1h, const __nv_bfloat16* __restrict__ A1l,
    const __nv_bfloat16* __restrict__ B1h, const __nv_bfloat16* __restrict__ B1l,
    const __nv_bfloat16* __restrict__ A2h, const __nv_bfloat16* __restrict__ A2l,
    const __nv_bfloat16* __restrict__ B2h, const __nv_bfloat16* __restrict__ B2l,
    const float* __restrict__ ACCsrc, float* __restrict__ Dout, int M,
    const float* __restrict__ bias1, const float* __restrict__ bias2, int relu,
    __nv_bfloat16* __restrict__ Oh, __nv_bfloat16* __restrict__ Ol)
{
    extern __shared__ uint32_t sb[];
    uint32_t* s1h = sb;                  // [128][68]
    uint32_t* s1l = sb + 128 * 68;
    uint32_t* s2h = sb + 2 * 128 * 68;
    uint32_t* s2l = sb + 3 * 128 * 68;
    int tid = threadIdx.x;
    for (int i = tid; i < 128 * 64; i += 256) {
        int r = i >> 6, c = i & 63;
        s1h[r * 68 + c] = reinterpret_cast<const uint32_t*>(B1h)[i];
        s1l[r * 68 + c] = reinterpret_cast<const uint32_t*>(B1l)[i];
        s2h[r * 68 + c] = reinterpret_cast<const uint32_t*>(B2h)[i];
        s2l[r * 68 + c] = reinterpret_cast<const uint32_t*>(B2l)[i];
    }
    __syncthreads();

    int warp = tid >> 5, lane = tid & 31;
    int g = lane >> 2, t4 = lane & 3;
    int m0 = blockIdx.x * 128 + warp * 16;
    const uint32_t* a1hp = reinterpret_cast<const uint32_t*>(A1h) + (size_t)m0 * 64;
    const uint32_t* a1lp = reinterpret_cast<const uint32_t*>(A1l) + (size_t)m0 * 64;
    const uint32_t* a2hp = reinterpret_cast<const uint32_t*>(A2h) + (size_t)m0 * 64;
    const uint32_t* a2lp = reinterpret_cast<const uint32_t*>(A2l) + (size_t)m0 * 64;

    float acc[16][4];
#pragma unroll
    for (int nf = 0; nf < 16; nf++)
#pragma unroll
        for (int j = 0; j < 4; j++) acc[nf][j] = 0.f;

#pragma unroll 1
    for (int k0 = 0; k0 < 8; k0++) {
        int kb = k0 * 8;
        int o0 = g * 64 + kb + t4, o1 = (g + 8) * 64 + kb + t4;
        uint32_t p0h = a1hp[o0], p1h = a1hp[o1], p2h = a1hp[o0 + 4], p3h = a1hp[o1 + 4];
        uint32_t p0l = a1lp[o0], p1l = a1lp[o1], p2l = a1lp[o0 + 4], p3l = a1lp[o1 + 4];
        uint32_t q0h = a2hp[o0], q1h = a2hp[o1], q2h = a2hp[o0 + 4], q3h = a2hp[o1 + 4];
        uint32_t q0l = a2lp[o0], q1l = a2lp[o1], q2l = a2lp[o0 + 4], q3l = a2lp[o1 + 4];
#pragma unroll
        for (int nf = 0; nf < 16; nf++) {
            int n = nf * 8 + g;
            const uint32_t* b1h = s1h + n * 68;
            const uint32_t* b1l = s1l + n * 68;
            const uint32_t* b2h = s2h + n * 68;
            const uint32_t* b2l = s2l + n * 68;
            uint32_t x0h = b1h[kb + t4], x1h = b1h[kb + t4 + 4];
            uint32_t x0l = b1l[kb + t4], x1l = b1l[kb + t4 + 4];
            uint32_t y0h = b2h[kb + t4], y1h = b2h[kb + t4 + 4];
            uint32_t y0l = b2l[kb + t4], y1l = b2l[kb + t4 + 4];
            mma16816(acc[nf], p0h, p1h, p2h, p3h, x0h, x1h);
            mma16816(acc[nf], p0h, p1h, p2h, p3h, x0l, x1l);
            mma16816(acc[nf], p0l, p1l, p2l, p3l, x0h, x1h);
            mma16816(acc[nf], q0h, q1h, q2h, q3h, y0h, y1h);
            mma16816(acc[nf], q0h, q1h, q2h, q3h, y0l, y1l);
            mma16816(acc[nf], q0l, q1l, q2l, q3l, y0h, y1h);
        }
    }

    int r0 = m0 + g, r1 = m0 + g + 8;
#pragma unroll
    for (int nf = 0; nf < 16; nf++) {
        int c = nf * 8 + t4 * 2;
        float bx = 0.f, by = 0.f;
        if (bias1) { float2 b = *reinterpret_cast<const float2*>(&bias1[c]); bx += b.x; by += b.y; }
        if (bias2) { float2 b = *reinterpret_cast<const float2*>(&bias2[c]); bx += b.x; by += b.y; }
        if (r0 < M) {
            float2 o = make_float2(acc[nf][0] + bx, acc[nf][1] + by);
            if (ACCsrc) { float2 d = *reinterpret_cast<const float2*>(&ACCsrc[(size_t)r0 * 128 + c]); o.x += d.x; o.y += d.y; }
            if (relu) { o.x = fmaxf(o.x, 0.f); o.y = fmaxf(o.y, 0.f); }
            if (Dout) *reinterpret_cast<float2*>(&Dout[(size_t)r0 * 128 + c]) = o;
            if (Oh) {
                uint32_t h, l;
                split2(o.x, o.y, h, l);
                *reinterpret_cast<uint32_t*>(&Oh[(size_t)r0 * 128 + c]) = h;
                *reinterpret_cast<uint32_t*>(&Ol[(size_t)r0 * 128 + c]) = l;
            }
        }
        if (r1 < M) {
            float2 o = make_float2(acc[nf][2] + bx, acc[nf][3] + by);
            if (ACCsrc) { float2 d = *reinterpret_cast<const float2*>(&ACCsrc[(size_t)r1 * 128 + c]); o.x += d.x; o.y += d.y; }
            if (relu) { o.x = fmaxf(o.x, 0.f); o.y = fmaxf(o.y, 0.f); }
            if (Dout) *reinterpret_cast<float2*>(&Dout[(size_t)r1 * 128 + c]) = o;
            if (Oh) {
                uint32_t h, l;
                split2(o.x, o.y, h, l);
                *reinterpret_cast<uint32_t*>(&Oh[(size_t)r1 * 128 + c]) = h;
                *reinterpret_cast<uint32_t*>(&Ol[(size_t)r1 * 128 + c]) = l;
            }
        }
    }
}

// ---------------- gathers (warp per dst row, no atomics) ----------------
__global__ void __launch_bounds__(256) gather_mean_split_kernel(
    const int* __restrict__ off, const int* __restrict__ lst,
    const float* __restrict__ X,
    __nv_bfloat16* __restrict__ Oh, __nv_bfloat16* __restrict__ Ol, int n)
{
    int w = (blockIdx.x * blockDim.x + threadIdx.x) >> 5;
    if (w >= n) return;
    int lane = threadIdx.x & 31;
    int s = off[w], e = off[w + 1];
    float4 a0 = make_float4(0.f, 0.f, 0.f, 0.f);
    float4 a1 = make_float4(0.f, 0.f, 0.f, 0.f);
    int i = s;
    for (; i + 1 < e; i += 2) {
        int p0 = lst[i], p1 = lst[i + 1];
        float4 v0 = *reinterpret_cast<const float4*>(&X[(size_t)p0 * HID + lane * 4]);
        float4 v1 = *reinterpret_cast<const float4*>(&X[(size_t)p1 * HID + lane * 4]);
        a0.x += v0.x; a0.y += v0.y; a0.z += v0.z; a0.w += v0.w;
        a1.x += v1.x; a1.y += v1.y; a1.z += v1.z; a1.w += v1.w;
    }
    if (i < e) {
        int p0 = lst[i];
        float4 v0 = *reinterpret_cast<const float4*>(&X[(size_t)p0 * HID + lane * 4]);
        a0.x += v0.x; a0.y += v0.y; a0.z += v0.z; a0.w += v0.w;
    }
    float inv = 1.0f / fmaxf((float)(e - s), 1.0f);
    float ox = (a0.x + a1.x) * inv, oy = (a0.y + a1.y) * inv;
    float oz = (a0.z + a1.z) * inv, ow = (a0.w + a1.w) * inv;
    uint2 uh, ul;
    split2(ox, oy, uh.x, ul.x);
    split2(oz, ow, uh.y, ul.y);
    reinterpret_cast<uint2*>(&Oh[(size_t)w * HID])[lane] = uh;
    reinterpret_cast<uint2*>(&Ol[(size_t)w * HID])[lane] = ul;
}

// GCN pre-aggregation over x_m (both directions), outputs split GF/GR
__global__ void __launch_bounds__(256) gcn_pre_kernel(const float* __restrict__ X)
{
    int w = (blockIdx.x * blockDim.x + threadIdx.x) >> 5;
    if (w >= NM) return;
    int lane = threadIdx.x & 31;
    size_t ro = (size_t)w * HID + lane * 4;

    float4 aF = make_float4(0.f, 0.f, 0.f, 0.f);
    {
        int s = g_offF[w], e = g_offF[w + 1];
        float4 t1 = make_float4(0.f, 0.f, 0.f, 0.f);
        int i = s;
        for (; i + 1 < e; i += 2) {
            int p0 = g_lstF[i], p1 = g_lstF[i + 1];
            float w0 = g_dF[p0], w1 = g_dF[p1];
            float4 v0 = *reinterpret_cast<const float4*>(&X[(size_t)p0 * HID + lane * 4]);
            float4 v1 = *reinterpret_cast<const float4*>(&X[(size_t)p1 * HID + lane * 4]);
            aF.x += w0 * v0.x; aF.y += w0 * v0.y; aF.z += w0 * v0.z; aF.w += w0 * v0.w;
            t1.x += w1 * v1.x; t1.y += w1 * v1.y; t1.z += w1 * v1.z; t1.w += w1 * v1.w;
        }
        if (i < e) {
            int p0 = g_lstF[i];
            float w0 = g_dF[p0];
            float4 v0 = *reinterpret_cast<const float4*>(&X[(size_t)p0 * HID + lane * 4]);
            aF.x += w0 * v0.x; aF.y += w0 * v0.y; aF.z += w0 * v0.z; aF.w += w0 * v0.w;
        }
        aF.x += t1.x; aF.y += t1.y; aF.z += t1.z; aF.w += t1.w;
    }
    float4 aR = make_float4(0.f, 0.f, 0.f, 0.f);
    {
        int s = g_offR[w], e = g_offR[w + 1];
        float4 t1 = make_float4(0.f, 0.f, 0.f, 0.f);
        int i = s;
        for (; i + 1 < e; i += 2) {
            int p0 = g_lstR[i], p1 = g_lstR[i + 1];
            float w0 = g_dR[p0], w1 = g_dR[p1];
            float4 v0 = *reinterpret_cast<const float4*>(&X[(size_t)p0 * HID + lane * 4]);
            float4 v1 = *reinterpret_cast<const float4*>(&X[(size_t)p1 * HID + lane * 4]);
            aR.x += w0 * v0.x; aR.y += w0 * v0.y; aR.z += w0 * v0.z; aR.w += w0 * v0.w;
            t1.x += w1 * v1.x; t1.y += w1 * v1.y; t1.z += w1 * v1.z; t1.w += w1 * v1.w;
        }
        if (i < e) {
            int p0 = g_lstR[i];
            float w0 = g_dR[p0];
            float4 v0 = *reinterpret_cast<const float4*>(&X[(size_t)p0 * HID + lane * 4]);
            aR.x += w0 * v0.x; aR.y += w0 * v0.y; aR.z += w0 * v0.z; aR.w += w0 * v0.w;
        }
        aR.x += t1.x; aR.y += t1.y; aR.z += t1.z; aR.w += t1.w;
    }

    float f = g_dF[w], r = g_dR[w];
    float f2 = f * f, r2 = r * r;
    float4 xv = *reinterpret_cast<const float4*>(&X[ro]);
    float fx = f * aF.x + f2 * xv.x, fy = f * aF.y + f2 * xv.y;
    float fz = f * aF.z + f2 * xv.z, fw = f * aF.w + f2 * xv.w;
    float rx = r * aR.x + r2 * xv.x, ry = r * aR.y + r2 * xv.y;
    float rz = r * aR.z + r2 * xv.z, rw = r * aR.w + r2 * xv.w;
    uint2 uh, ul;
    split2(fx, fy, uh.x, ul.x);
    split2(fz, fw, uh.y, ul.y);
    reinterpret_cast<uint2*>(&g_GFh[(size_t)w * HID])[lane] = uh;
    reinterpret_cast<uint2*>(&g_GFl[(size_t)w * HID])[lane] = ul;
    split2(rx, ry, uh.x, ul.x);
    split2(rz, rw, uh.y, ul.y);
    reinterpret_cast<uint2*>(&g_GRh[(size_t)w * HID])[lane] = uh;
    reinterpret_cast<uint2*>(&g_GRl[(size_t)w * HID])[lane] = ul;
}

// ---------------- classifier ----------------
__global__ void __launch_bounds__(256) classify_kernel(
    const int* __restrict__ ls, const int* __restrict__ ld,
    const float* __restrict__ XS, const float* __restrict__ XM,
    float* __restrict__ out, int E)
{
    long long t = (long long)blockIdx.x * blockDim.x + threadIdx.x;
    int e = (int)(t >> 5);
    if (e >= E) return;
    int lane = (int)(t & 31);
    int s = ls[e], d = ld[e];
    float4 a = *reinterpret_cast<const float4*>(&XS[(size_t)s * HID + lane * 4]);
    float4 b = *reinterpret_cast<const float4*>(&XM[(size_t)d * HID + lane * 4]);
    float p = a.x * b.x + a.y * b.y + a.z * b.z + a.w * b.w;
#pragma unroll
    for (int o = 16; o > 0; o >>= 1) p += __shfl_xor_sync(0xffffffffu, p, o);
    if (lane == 0) out[e] = p;
}

// ---------------- host ----------------
extern "C" void kernel_launch(void* const* d_in, const int* in_sizes, int n_in,
                              void* d_out, int out_size)
{
    const int*   s2m_src = (const int*)d_in[0];
    const int*   s2m_dst = (const int*)d_in[1];
    const int*   m2m_src = (const int*)d_in[2];
    const int*   m2m_dst = (const int*)d_in[3];
    const int*   lbl_src = (const int*)d_in[4];
    const int*   lbl_dst = (const int*)d_in[5];
    const float* srna    = (const float*)d_in[6];
    const float* mrna    = (const float*)d_in[7];
    const float* sWl     = (const float*)d_in[8];
    const float* sbl     = (const float*)d_in[9];
    const float* sWr     = (const float*)d_in[10];
    const float* rWl     = (const float*)d_in[11];
    const float* rbl     = (const float*)d_in[12];
    const float* rWr     = (const float*)d_in[13];
    const float* gFW     = (const float*)d_in[14];
    const float* gFb     = (const float*)d_in[15];
    const float* gRW     = (const float*)d_in[16];
    const float* gRb     = (const float*)d_in[17];

    const int Es2m = in_sizes[0];
    const int Em2m = in_sizes[2];
    const int Elbl = in_sizes[4];

    float *xs0, *xs1, *xm0, *xm1, *macc;
    int *offMd, *offSs, *lstMd, *lstSs;
    __nv_bfloat16 *Xmh, *Xml, *Magh, *Magl, *GFh, *GFl, *GRh, *GRl;
    __nv_bfloat16 *Xsh, *Xsl, *Sagh, *Sagl, *Wth, *Wtl;
    cudaGetSymbolAddress((void**)&xs0, g_xs0);
    cudaGetSymbolAddress((void**)&xs1, g_xs1);
    cudaGetSymbolAddress((void**)&xm0, g_xm0);
    cudaGetSymbolAddress((void**)&xm1, g_xm1);
    cudaGetSymbolAddress((void**)&macc, g_macc);
    cudaGetSymbolAddress((void**)&offMd, g_offMd);
    cudaGetSymbolAddress((void**)&offSs, g_offSs);
    cudaGetSymbolAddress((void**)&lstMd, g_lstMd);
    cudaGetSymbolAddress((void**)&lstSs, g_lstSs);
    cudaGetSymbolAddress((void**)&Xmh, g_Xmh);
    cudaGetSymbolAddress((void**)&Xml, g_Xml);
    cudaGetSymbolAddress((void**)&Magh, g_Magh);
    cudaGetSymbolAddress((void**)&Magl, g_Magl);
    cudaGetSymbolAddress((void**)&GFh, g_GFh);
    cudaGetSymbolAddress((void**)&GFl, g_GFl);
    cudaGetSymbolAddress((void**)&GRh, g_GRh);
    cudaGetSymbolAddress((void**)&GRl, g_GRl);
    cudaGetSymbolAddress((void**)&Xsh, g_Xsh);
    cudaGetSymbolAddress((void**)&Xsl, g_Xsl);
    cudaGetSymbolAddress((void**)&Sagh, g_Sagh);
    cudaGetSymbolAddress((void**)&Sagl, g_Sagl);
    cudaGetSymbolAddress((void**)&Wth, g_Wth);
    cudaGetSymbolAddress((void**)&Wtl, g_Wtl);

    cudaFuncSetAttribute(gemm_dual,
                         cudaFuncAttributeMaxDynamicSharedMemorySize, DUAL_SMEM);

    static cudaStream_t s2 = nullptr;
    static cudaEvent_t evCsr, evP1[NLAYERS], evM[NLAYERS], evS;
    if (!s2) {
        cudaStreamCreateWithFlags(&s2, cudaStreamNonBlocking);
        cudaEventCreateWithFlags(&evCsr, cudaEventDisableTiming);
        cudaEventCreateWithFlags(&evS, cudaEventDisableTiming);
        for (int i = 0; i < NLAYERS; i++) {
            cudaEventCreateWithFlags(&evP1[i], cudaEventDisableTiming);
            cudaEventCreateWithFlags(&evM[i], cudaEventDisableTiming);
        }
    }

    const size_t WSZ = (size_t)HID * HID;

    // ---- fork: side does initial feature splits; main: weight splits + CSR ----
    static cudaEvent_t ev0 = nullptr;
    if (!ev0) cudaEventCreateWithFlags(&ev0, cudaEventDisableTiming);
    cudaEventRecord(ev0, 0);
    cudaStreamWaitEvent(s2, ev0, 0);
    split_kernel<<<(NM * 32 + 255) / 256, 256, 0, s2>>>(mrna, Xmh, Xml, NM * 32);
    split_kernel<<<(NS * 32 + 255) / 256, 256, 0, s2>>>(srna, Xsh, Xsl, NS * 32);

    for (int l = 0; l < NLAYERS; l++) {
        const float* Ws[6] = { sWl + l * WSZ, sWr + l * WSZ, rWl + l * WSZ,
                               rWr + l * WSZ, gFW + l * WSZ, gRW + l * WSZ };
        for (int j = 0; j < 6; j++) {
            int slot = l * 6 + j;
            wsplit_kernel<<<(HID * HID + 255) / 256, 256>>>(Ws[j], Wth + slot * WSZ, Wtl + slot * WSZ);
        }
    }
    zero_counts_kernel<<<(NM + 255) / 256, 256>>>();
    hist_s2m_kernel<<<(Es2m + 255) / 256, 256>>>(s2m_src, s2m_dst, Es2m);
    hist_m2m_kernel<<<(Em2m + 255) / 256, 256>>>(m2m_src, m2m_dst, Em2m);
    {
        dim3 g((NM + 1023) / 1024, 4);
        scan_partial_kernel<<<g, 1024>>>();
        scan_fix_kernel<<<g, 1024>>>();
    }
    fill_s2m_kernel<<<(Es2m + 255) / 256, 256>>>(s2m_src, s2m_dst, Es2m);
    fill_m2m_kernel<<<(Em2m + 255) / 256, 256>>>(m2m_src, m2m_dst, Em2m);
    deg_kernel<<<(NM + 255) / 256, 256>>>();
    cudaEventRecord(evCsr, 0);
    cudaStreamWaitEvent(s2, evCsr, 0);   // side gathers need CSR

    const float* xsi = srna;
    const float* xmi = mrna;
    const unsigned gm = NMP / 128;   // 782
    const unsigned gs = NSP / 128;   // 157

    for (int l = 0; l < NLAYERS; l++) {
        float* xso = (l == 0) ? xs0 : xs1;
        float* xmo = (l == 0) ? xm0 : xm1;
        int s6 = l * 6;

        if (l > 0) cudaStreamWaitEvent(s2, evM[l - 1], 0);  // xm + Xm split from prev pair2

        // ---- side stream: Md gather -> pair1 -> Ss gather -> s-pair ----
        gather_mean_split_kernel<<<(NM * 32 + 255) / 256, 256, 0, s2>>>(offMd, lstMd, xsi, Magh, Magl, NM);
        gemm_dual<<<gm, 256, DUAL_SMEM, s2>>>(
            Xmh, Xml, Wth + (s6 + 1) * WSZ, Wtl + (s6 + 1) * WSZ,     // x_m @ sWr
            Magh, Magl, Wth + (s6 + 0) * WSZ, Wtl + (s6 + 0) * WSZ,   // mean @ sWl
            nullptr, macc, NM, sbl + l * HID, nullptr, 0, nullptr, nullptr);
        cudaEventRecord(evP1[l], s2);
        gather_mean_split_kernel<<<(NS * 32 + 255) / 256, 256, 0, s2>>>(offSs, lstSs, xmi, Sagh, Sagl, NS);
        gemm_dual<<<gs, 256, DUAL_SMEM, s2>>>(
            Xsh, Xsl, Wth + (s6 + 3) * WSZ, Wtl + (s6 + 3) * WSZ,     // x_s @ rWr
            Sagh, Sagl, Wth + (s6 + 2) * WSZ, Wtl + (s6 + 2) * WSZ,   // mean @ rWl
            nullptr, xso, NS, rbl + l * HID, nullptr, 1, Xsh, Xsl);
        if (l == NLAYERS - 1) cudaEventRecord(evS, s2);

        // ---- main stream: gcn_pre (memory) overlaps pair1 (tensor) ----
        gcn_pre_kernel<<<(NM * 32 + 255) / 256, 256>>>(xmi);
        cudaStreamWaitEvent(0, evP1[l], 0);
        gemm_dual<<<gm, 256, DUAL_SMEM>>>(
            GFh, GFl, Wth + (s6 + 4) * WSZ, Wtl + (s6 + 4) * WSZ,     // gF_in @ gFW
            GRh, GRl, Wth + (s6 + 5) * WSZ, Wtl + (s6 + 5) * WSZ,     // gR_in @ gRW
            macc, xmo, NM, gFb + l * HID, gRb + l * HID, 1, Xmh, Xml);
        cudaEventRecord(evM[l], 0);

        xsi = xso;
        xmi = xmo;
    }

    cudaStreamWaitEvent(0, evS, 0);
    {
        long long th = (long long)Elbl * 32;
        classify_kernel<<<(unsigned)((th + 255) / 256), 256>>>(lbl_src, lbl_dst, xsi, xmi, (float*)d_out, Elbl);
    }
}